// round 10
// baseline (speedup 1.0000x reference)
#include <cuda_runtime.h>
#include <cuda_bf16.h>
#include <math.h>
#include <stdint.h>

#define B_  8
#define L_  4096
#define D_  1024
#define K_  256
#define N3_ 3072
#define BL_ (B_*L_)

typedef __nv_bfloat16 bf16;

// ---------------- scratch (__device__ globals) ------------------------------
__device__ bf16  g_xh [(size_t)BL_ * D_],  g_xl [(size_t)BL_ * D_];
__device__ bf16  g_wh [(size_t)D_ * N3_],  g_wl [(size_t)D_ * N3_];
__device__ bf16  g_hkh[(size_t)L_ * K_],   g_hkl[(size_t)L_ * K_];
__device__ bf16  g_hvh[(size_t)L_ * K_],   g_hvl[(size_t)L_ * K_];
__device__ bf16  g_qkvh[(size_t)BL_ * N3_], g_qkvl[(size_t)BL_ * N3_];
__device__ bf16  g_kph[(size_t)B_ * K_ * D_], g_kpl[(size_t)B_ * K_ * D_];
__device__ bf16  g_vph[(size_t)B_ * K_ * D_], g_vpl[(size_t)B_ * K_ * D_];
__device__ float g_sc [(size_t)BL_ * K_];
__device__ bf16  g_ph [(size_t)BL_ * K_],  g_pl [(size_t)BL_ * K_];

// ---------------- helpers ---------------------------------------------------
__device__ __forceinline__ uint32_t smem_u32(const void* p) {
    uint32_t a;
    asm("{ .reg .u64 t; cvta.to.shared.u64 t, %1; cvt.u32.u64 %0, t; }" : "=r"(a) : "l"(p));
    return a;
}
__device__ __forceinline__ void cp16(uint32_t saddr, const void* gaddr) {
    asm volatile("cp.async.cg.shared.global [%0], [%1], 16;" :: "r"(saddr), "l"(gaddr));
}
#define CP_COMMIT() asm volatile("cp.async.commit_group;" ::: "memory")
#define CP_WAIT0()  asm volatile("cp.async.wait_group 0;" ::: "memory")
#define CP_WAIT1()  asm volatile("cp.async.wait_group 1;" ::: "memory")

__device__ __forceinline__ void ldsm_x4(uint32_t* r, uint32_t addr) {
    asm volatile("ldmatrix.sync.aligned.m8n8.x4.shared.b16 {%0,%1,%2,%3}, [%4];"
                 : "=r"(r[0]), "=r"(r[1]), "=r"(r[2]), "=r"(r[3]) : "r"(addr));
}
__device__ __forceinline__ void ldsm_x4t(uint32_t* r, uint32_t addr) {
    asm volatile("ldmatrix.sync.aligned.m8n8.x4.trans.shared.b16 {%0,%1,%2,%3}, [%4];"
                 : "=r"(r[0]), "=r"(r[1]), "=r"(r[2]), "=r"(r[3]) : "r"(addr));
}
__device__ __forceinline__ void mma16816(float* d, const uint32_t* a, uint32_t b0, uint32_t b1) {
    asm volatile("mma.sync.aligned.m16n8k16.row.col.f32.bf16.bf16.f32 "
                 "{%0,%1,%2,%3}, {%4,%5,%6,%7}, {%8,%9}, {%0,%1,%2,%3};"
                 : "+f"(d[0]), "+f"(d[1]), "+f"(d[2]), "+f"(d[3])
                 : "r"(a[0]), "r"(a[1]), "r"(a[2]), "r"(a[3]), "r"(b0), "r"(b1));
}
__device__ __forceinline__ void pack_hl(float a, float b, uint32_t& h, uint32_t& l) {
    __nv_bfloat162 hv = __floats2bfloat162_rn(a, b);
    float2 hf = __bfloat1622float2(hv);
    __nv_bfloat162 lv = __floats2bfloat162_rn(a - hf.x, b - hf.y);
    h = *(uint32_t*)&hv;
    l = *(uint32_t*)&lv;
}

// ---------------------------------------------------------------------------
// presplit: fp32 -> hi/lo bf16
// ---------------------------------------------------------------------------
__global__ __launch_bounds__(256)
void presplit(const float* __restrict__ src, bf16* __restrict__ h, bf16* __restrict__ l)
{
    size_t i = ((size_t)blockIdx.x * 256 + threadIdx.x) * 4;
    float4 v = *(const float4*)(src + i);
    uint32_t h0, l0, h1, l1;
    pack_hl(v.x, v.y, h0, l0);
    pack_hl(v.z, v.w, h1, l1);
    *(uint2*)(h + i) = make_uint2(h0, h1);
    *(uint2*)(l + i) = make_uint2(l0, l1);
}

// ---------------------------------------------------------------------------
// Core bf16 hi/lo mma GEMM.
// CTA tile 256(M) x 128(N), 512 threads (warps 4m x 4n, warp tile 64x32),
// K-step 32, NS=3 cp.async pipeline, 1 barrier/stage.
// ---------------------------------------------------------------------------
#define NS 3

template<int TRA, int TRB, int OUTBF>
__device__ __forceinline__ void ghl_core(
    const bf16* __restrict__ Ah, const bf16* __restrict__ Al, int lda,
    const bf16* __restrict__ Bh, const bf16* __restrict__ Bl, int ldb,
    float* __restrict__ Cf, bf16* __restrict__ Ch, bf16* __restrict__ Cl, int ldc,
    int Kred, float scale, const float* __restrict__ bias, char* smem)
{
    constexpr int PA  = TRA ? 264 : 40;         // pitch (bf16 elems)
    constexpr int PB  = TRB ? 136 : 40;
    constexpr int SAe = TRA ? 32 * 264 : 256 * 40;
    constexpr int SBe = TRB ? 32 * 136 : 128 * 40;
    constexpr int STE = 2 * SAe + 2 * SBe;

    const int tid = threadIdx.x, lane = tid & 31, warp = tid >> 5;
    const int wm = (warp & 3) * 64, wn = (warp >> 2) * 32;
    const int m0 = blockIdx.y * 256, n0 = blockIdx.x * 128;

    const uint32_t sbase = smem_u32(smem);

    const int nt_row = lane & 15, nt_col = (lane >> 4) * 8;
    const int tr_krow = (lane & 7) + ((lane & 16) >> 1);
    const int tr_mcol = lane & 8;

    // copy slots: A 2/thread (1024 x 16B), B 1/thread (512 x 16B)
    int aoff[2]; size_t agof[2];
#pragma unroll
    for (int i = 0; i < 2; i++) {
        int idx = tid + i * 512;
        if (TRA) { int kr = idx >> 5, c = (idx & 31) * 8;
            aoff[i] = kr * PA + c;  agof[i] = (size_t)kr * lda + m0 + c; }
        else     { int r = idx >> 2, c = (idx & 3) * 8;
            aoff[i] = r * PA + c;   agof[i] = (size_t)(m0 + r) * lda + c; }
    }
    int boff; size_t bgof;
    if (TRB) { int kr = tid >> 4, c = (tid & 15) * 8;
        boff = kr * PB + c;  bgof = (size_t)kr * ldb + n0 + c; }
    else     { int r = tid >> 2,  c = (tid & 3) * 8;
        boff = r * PB + c;   bgof = (size_t)(n0 + r) * ldb + c; }

    auto issue_stage = [&](int buf, int k0) {
        uint32_t base = sbase + (uint32_t)(buf * STE) * 2;
        size_t ka = TRA ? (size_t)k0 * lda : (size_t)k0;
        size_t kb = TRB ? (size_t)k0 * ldb : (size_t)k0;
#pragma unroll
        for (int i = 0; i < 2; i++) {
            cp16(base + (uint32_t)aoff[i] * 2,         Ah + agof[i] + ka);
            cp16(base + (uint32_t)(SAe + aoff[i]) * 2, Al + agof[i] + ka);
        }
        cp16(base + (uint32_t)(2 * SAe + boff) * 2,       Bh + bgof + kb);
        cp16(base + (uint32_t)(2 * SAe + SBe + boff) * 2, Bl + bgof + kb);
        CP_COMMIT();
    };

    float acc[4][4][4] = {};

    const int NSTEP = Kred / 32;
    issue_stage(0, 0);
    issue_stage(1, 32);

    int buf = 0;
    for (int s = 0; s < NSTEP; s++) {
        if (s + 1 < NSTEP) CP_WAIT1(); else CP_WAIT0();
        __syncthreads();
        if (s + 2 < NSTEP) {
            int nb = buf + 2; if (nb >= NS) nb -= NS;
            issue_stage(nb, (s + 2) * 32);
        }

        const uint32_t aH = sbase + (uint32_t)(buf * STE) * 2;
        const uint32_t aL = aH + SAe * 2;
        const uint32_t bH = aH + 2 * SAe * 2;
        const uint32_t bL = bH + SBe * 2;

#pragma unroll
        for (int kk = 0; kk < 32; kk += 16) {
            uint32_t bh[2][4], bl[2][4];
#pragma unroll
            for (int nj = 0; nj < 2; nj++) {
                if (TRB) {
                    uint32_t off = (uint32_t)((kk + tr_krow) * PB + wn + nj * 16 + tr_mcol) * 2;
                    ldsm_x4t(bh[nj], bH + off);
                    ldsm_x4t(bl[nj], bL + off);
                } else {
                    uint32_t off = (uint32_t)((wn + nj * 16 + nt_row) * PB + kk + nt_col) * 2;
                    ldsm_x4(bh[nj], bH + off);
                    ldsm_x4(bl[nj], bL + off);
                }
            }
#pragma unroll
            for (int mi = 0; mi < 4; mi++) {
                uint32_t ah[4], al[4];
                if (TRA) {
                    uint32_t off = (uint32_t)((kk + tr_krow) * PA + wm + mi * 16 + tr_mcol) * 2;
                    ldsm_x4t(ah, aH + off);
                    ldsm_x4t(al, aL + off);
                } else {
                    uint32_t off = (uint32_t)((wm + mi * 16 + nt_row) * PA + kk + nt_col) * 2;
                    ldsm_x4(ah, aH + off);
                    ldsm_x4(al, aL + off);
                }
#pragma unroll
                for (int ni = 0; ni < 4; ni++) {
                    uint32_t b0 = bh[ni >> 1][ni & 1], b1 = bh[ni >> 1][(ni & 1) + 2];
                    mma16816(acc[mi][ni], ah, b0, b1);
                    mma16816(acc[mi][ni], al, b0, b1);
                    mma16816(acc[mi][ni], ah, bl[ni >> 1][ni & 1], bl[ni >> 1][(ni & 1) + 2]);
                }
            }
        }
        if (++buf >= NS) buf = 0;
    }

#pragma unroll
    for (int mi = 0; mi < 4; mi++) {
#pragma unroll
        for (int ni = 0; ni < 4; ni++) {
            int n = n0 + wn + ni * 8 + (lane & 3) * 2;
            int m = m0 + wm + mi * 16 + (lane >> 2);
            float bx = 0.f, by = 0.f;
            if (bias) { float2 bv = *(const float2*)(bias + n); bx = bv.x; by = bv.y; }
            float v00 = acc[mi][ni][0] * scale + bx, v01 = acc[mi][ni][1] * scale + by;
            float v10 = acc[mi][ni][2] * scale + bx, v11 = acc[mi][ni][3] * scale + by;
            if (OUTBF) {
                uint32_t h0, l0, h1, l1;
                pack_hl(v00, v01, h0, l0);
                pack_hl(v10, v11, h1, l1);
                *(uint32_t*)(Ch + (size_t)m * ldc + n)       = h0;
                *(uint32_t*)(Cl + (size_t)m * ldc + n)       = l0;
                *(uint32_t*)(Ch + (size_t)(m + 8) * ldc + n) = h1;
                *(uint32_t*)(Cl + (size_t)(m + 8) * ldc + n) = l1;
            } else {
                float* p0 = Cf + (size_t)m * ldc + n;
                float* p1 = Cf + (size_t)(m + 8) * ldc + n;
                p0[0] = v00; p0[1] = v01;
                p1[0] = v10; p1[1] = v11;
            }
        }
    }
}

// ---------------- wrappers --------------------------------------------------
__global__ __launch_bounds__(512)
void k_gemm1(const bf16* xh, const bf16* xl, const bf16* wh, const bf16* wl,
             const float* bias, bf16* qkvh, bf16* qkvl)
{
    extern __shared__ char sm[];
    ghl_core<0, 1, 1>(xh, xl, D_, wh, wl, N3_,
                      nullptr, qkvh, qkvl, N3_, D_, 1.f, bias, sm);
}

__global__ __launch_bounds__(512)
void k_proj(const bf16* hkh, const bf16* hkl, const bf16* hvh, const bf16* hvl,
            const bf16* qkvh, const bf16* qkvl,
            bf16* kph, bf16* kpl, bf16* vph, bf16* vpl)
{
    extern __shared__ char sm[];
    int p = blockIdx.z & 1, b = blockIdx.z >> 1;
    const bf16* Ah = p ? hvh : hkh;
    const bf16* Al = p ? hvl : hkl;
    const bf16* Bh = qkvh + (size_t)b * L_ * N3_ + (1 + p) * D_;
    const bf16* Bl = qkvl + (size_t)b * L_ * N3_ + (1 + p) * D_;
    bf16* Ch = (p ? vph : kph) + (size_t)b * K_ * D_;
    bf16* Cl = (p ? vpl : kpl) + (size_t)b * K_ * D_;
    ghl_core<1, 1, 1>(Ah, Al, K_, Bh, Bl, N3_,
                      nullptr, Ch, Cl, D_, L_, 1.f, nullptr, sm);
}

__global__ __launch_bounds__(512)
void k_scores(const bf16* qkvh, const bf16* qkvl, const bf16* kph, const bf16* kpl,
              float* sc)
{
    extern __shared__ char sm[];
    int b = blockIdx.z;
    ghl_core<0, 0, 0>(qkvh + (size_t)b * L_ * N3_, qkvl + (size_t)b * L_ * N3_, N3_,
                      kph + (size_t)b * K_ * D_, kpl + (size_t)b * K_ * D_, D_,
                      sc + (size_t)b * L_ * K_, nullptr, nullptr, K_,
                      D_, 0.03125f, nullptr, sm);
}

__global__ __launch_bounds__(512)
void k_out(const bf16* ph, const bf16* pl, const bf16* vph, const bf16* vpl,
           float* out)
{
    extern __shared__ char sm[];
    int b = blockIdx.z;
    ghl_core<0, 1, 0>(ph + (size_t)b * L_ * K_, pl + (size_t)b * L_ * K_, K_,
                      vph + (size_t)b * K_ * D_, vpl + (size_t)b * K_ * D_, D_,
                      out + (size_t)b * L_ * D_, nullptr, nullptr, D_,
                      K_, 1.f, nullptr, sm);
}

// ---------------------------------------------------------------------------
// softmax over K=256 -> hi/lo bf16 weights
// ---------------------------------------------------------------------------
__global__ __launch_bounds__(256)
void softmax_ps(const float* __restrict__ S, bf16* __restrict__ Ph, bf16* __restrict__ Pl)
{
    int warp = threadIdx.x >> 5, lane = threadIdx.x & 31;
    size_t row = (size_t)blockIdx.x * 8 + warp;
    const float* p = S + row * K_;

    float v[8];
    float m = -INFINITY;
#pragma unroll
    for (int i = 0; i < 8; i++) { v[i] = p[lane + i * 32]; m = fmaxf(m, v[i]); }
#pragma unroll
    for (int o = 16; o > 0; o >>= 1) m = fmaxf(m, __shfl_xor_sync(0xffffffffu, m, o));
    float s = 0.f;
#pragma unroll
    for (int i = 0; i < 8; i++) { v[i] = __expf(v[i] - m); s += v[i]; }
#pragma unroll
    for (int o = 16; o > 0; o >>= 1) s += __shfl_xor_sync(0xffffffffu, s, o);
    float inv = 1.f / s;
#pragma unroll
    for (int i = 0; i < 8; i++) {
        int kc = lane + i * 32;
        float w = v[i] * inv;
        bf16 h = __float2bfloat16_rn(w);
        bf16 lo = __float2bfloat16_rn(w - __bfloat162float(h));
        Ph[row * K_ + kc] = h;
        Pl[row * K_ + kc] = lo;
    }
}

// ---------------------------------------------------------------------------
extern "C" void kernel_launch(void* const* d_in, const int* in_sizes, int n_in,
                              void* d_out, int out_size)
{
    const float* x    = (const float*)d_in[0];
    const float* W    = (const float*)d_in[1];
    const float* bias = (const float*)d_in[2];
    const float* Hk   = (const float*)d_in[3];
    const float* Hv   = (const float*)d_in[4];
    float*       out  = (float*)d_out;

    bf16 *xh, *xl, *wh, *wl, *hkh, *hkl, *hvh, *hvl;
    bf16 *qkvh, *qkvl, *kph, *kpl, *vph, *vpl, *ph, *pl;
    float *sc;
    cudaGetSymbolAddress((void**)&xh, g_xh);   cudaGetSymbolAddress((void**)&xl, g_xl);
    cudaGetSymbolAddress((void**)&wh, g_wh);   cudaGetSymbolAddress((void**)&wl, g_wl);
    cudaGetSymbolAddress((void**)&hkh, g_hkh); cudaGetSymbolAddress((void**)&hkl, g_hkl);
    cudaGetSymbolAddress((void**)&hvh, g_hvh); cudaGetSymbolAddress((void**)&hvl, g_hvl);
    cudaGetSymbolAddress((void**)&qkvh, g_qkvh); cudaGetSymbolAddress((void**)&qkvl, g_qkvl);
    cudaGetSymbolAddress((void**)&kph, g_kph); cudaGetSymbolAddress((void**)&kpl, g_kpl);
    cudaGetSymbolAddress((void**)&vph, g_vph); cudaGetSymbolAddress((void**)&vpl, g_vpl);
    cudaGetSymbolAddress((void**)&ph, g_ph);   cudaGetSymbolAddress((void**)&pl, g_pl);
    cudaGetSymbolAddress((void**)&sc, g_sc);

    // stage elems: NT = 2*10240+2*4352 = 29184; TT = 2*8448+2*4352 = 25600;
    //              NN = 2*10240+2*5120 = 30720.  bytes = NS * elems * 2
    const int SZ_NT = NS * 29184 * 2;   // 175104
    const int SZ_TT = NS * 25600 * 2;   // 153600
    const int SZ_NN = NS * 30720 * 2;   // 184320
    cudaFuncSetAttribute(k_gemm1,  cudaFuncAttributeMaxDynamicSharedMemorySize, SZ_NT);
    cudaFuncSetAttribute(k_proj,   cudaFuncAttributeMaxDynamicSharedMemorySize, SZ_TT);
    cudaFuncSetAttribute(k_scores, cudaFuncAttributeMaxDynamicSharedMemorySize, SZ_NN);
    cudaFuncSetAttribute(k_out,    cudaFuncAttributeMaxDynamicSharedMemorySize, SZ_NT);

    presplit<<<(size_t)BL_ * D_ / 1024, 256>>>(x, xh, xl);
    presplit<<<(size_t)D_ * N3_ / 1024, 256>>>(W, wh, wl);
    presplit<<<(size_t)L_ * K_ / 1024, 256>>>(Hk, hkh, hkl);
    presplit<<<(size_t)L_ * K_ / 1024, 256>>>(Hv, hvh, hvl);

    // 1) qkv = x @ W + bias
    k_gemm1<<<dim3(N3_ / 128, BL_ / 256, 1), 512, SZ_NT>>>(xh, xl, wh, wl, bias, qkvh, qkvl);

    // 2) K_proj / V_proj = H^T @ {k,v}   (M=256 in one tile; z = b*2+p)
    k_proj<<<dim3(D_ / 128, 1, 2 * B_), 512, SZ_TT>>>(
        hkh, hkl, hvh, hvl, qkvh, qkvl, kph, kpl, vph, vpl);

    // 3) scores = q @ K_proj^T / 32
    k_scores<<<dim3(K_ / 128, L_ / 256, B_), 512, SZ_NN>>>(qkvh, qkvl, kph, kpl, sc);

    // 4) softmax
    softmax_ps<<<BL_ / 8, 256>>>(sc, ph, pl);

    // 5) out = P @ V_proj
    k_out<<<dim3(D_ / 128, L_ / 256, B_), 512, SZ_NT>>>(ph, pl, vph, vpl, out);
}

// round 11
// speedup vs baseline: 1.0808x; 1.0808x over previous
#include <cuda_runtime.h>
#include <cuda_bf16.h>
#include <math.h>
#include <stdint.h>

#define B_  8
#define L_  4096
#define D_  1024
#define K_  256
#define N3_ 3072
#define BL_ (B_*L_)

typedef __nv_bfloat16 bf16;

// ---------------- scratch (__device__ globals) ------------------------------
__device__ bf16  g_xh [(size_t)BL_ * D_],  g_xl [(size_t)BL_ * D_];
__device__ bf16  g_wh [(size_t)D_ * N3_],  g_wl [(size_t)D_ * N3_];
__device__ bf16  g_hkh[(size_t)L_ * K_],   g_hkl[(size_t)L_ * K_];
__device__ bf16  g_hvh[(size_t)L_ * K_],   g_hvl[(size_t)L_ * K_];
__device__ bf16  g_qkvh[(size_t)BL_ * N3_], g_qkvl[(size_t)BL_ * N3_];
__device__ bf16  g_kph[(size_t)B_ * K_ * D_], g_kpl[(size_t)B_ * K_ * D_];
__device__ bf16  g_vph[(size_t)B_ * K_ * D_], g_vpl[(size_t)B_ * K_ * D_];
__device__ float g_sc [(size_t)BL_ * K_];
__device__ bf16  g_ph [(size_t)BL_ * K_],  g_pl [(size_t)BL_ * K_];

// ---------------- helpers ---------------------------------------------------
__device__ __forceinline__ uint32_t smem_u32(const void* p) {
    uint32_t a;
    asm("{ .reg .u64 t; cvta.to.shared.u64 t, %1; cvt.u32.u64 %0, t; }" : "=r"(a) : "l"(p));
    return a;
}
__device__ __forceinline__ void cp16(uint32_t saddr, const void* gaddr) {
    asm volatile("cp.async.cg.shared.global [%0], [%1], 16;" :: "r"(saddr), "l"(gaddr));
}
#define CP_COMMIT() asm volatile("cp.async.commit_group;" ::: "memory")
#define CP_WAIT0()  asm volatile("cp.async.wait_group 0;" ::: "memory")
#define CP_WAIT1()  asm volatile("cp.async.wait_group 1;" ::: "memory")

__device__ __forceinline__ void ldsm_x4(uint32_t* r, uint32_t addr) {
    asm volatile("ldmatrix.sync.aligned.m8n8.x4.shared.b16 {%0,%1,%2,%3}, [%4];"
                 : "=r"(r[0]), "=r"(r[1]), "=r"(r[2]), "=r"(r[3]) : "r"(addr));
}
__device__ __forceinline__ void ldsm_x4t(uint32_t* r, uint32_t addr) {
    asm volatile("ldmatrix.sync.aligned.m8n8.x4.trans.shared.b16 {%0,%1,%2,%3}, [%4];"
                 : "=r"(r[0]), "=r"(r[1]), "=r"(r[2]), "=r"(r[3]) : "r"(addr));
}
__device__ __forceinline__ void mma16816(float* d, const uint32_t* a, uint32_t b0, uint32_t b1) {
    asm volatile("mma.sync.aligned.m16n8k16.row.col.f32.bf16.bf16.f32 "
                 "{%0,%1,%2,%3}, {%4,%5,%6,%7}, {%8,%9}, {%0,%1,%2,%3};"
                 : "+f"(d[0]), "+f"(d[1]), "+f"(d[2]), "+f"(d[3])
                 : "r"(a[0]), "r"(a[1]), "r"(a[2]), "r"(a[3]), "r"(b0), "r"(b1));
}
__device__ __forceinline__ void pack_hl(float a, float b, uint32_t& h, uint32_t& l) {
    __nv_bfloat162 hv = __floats2bfloat162_rn(a, b);
    float2 hf = __bfloat1622float2(hv);
    __nv_bfloat162 lv = __floats2bfloat162_rn(a - hf.x, b - hf.y);
    h = *(uint32_t*)&hv;
    l = *(uint32_t*)&lv;
}

// ---------------------------------------------------------------------------
// presplit: fp32 -> hi/lo bf16
// ---------------------------------------------------------------------------
__global__ __launch_bounds__(256)
void presplit(const float* __restrict__ src, bf16* __restrict__ h, bf16* __restrict__ l)
{
    size_t i = ((size_t)blockIdx.x * 256 + threadIdx.x) * 4;
    float4 v = *(const float4*)(src + i);
    uint32_t h0, l0, h1, l1;
    pack_hl(v.x, v.y, h0, l0);
    pack_hl(v.z, v.w, h1, l1);
    *(uint2*)(h + i) = make_uint2(h0, h1);
    *(uint2*)(l + i) = make_uint2(l0, l1);
}

// ---------------------------------------------------------------------------
// Core bf16 hi/lo mma GEMM, NS=2 cp.async, issue-before-wait schedule.
// CTA tile 128x128, 256 threads (warps 2m x 4n, warp tile 64x32), K-step 32.
// ---------------------------------------------------------------------------
#define PADN 40
#define PADT 136

template<int TRA, int TRB, int OUTBF>
__device__ __forceinline__ void ghl_core(
    const bf16* __restrict__ Ah, const bf16* __restrict__ Al, int lda,
    const bf16* __restrict__ Bh, const bf16* __restrict__ Bl, int ldb,
    float* __restrict__ Cf, bf16* __restrict__ Ch, bf16* __restrict__ Cl, int ldc,
    int Kred, float scale, const float* __restrict__ bias, char* smem)
{
    constexpr int SAe = TRA ? 32 * PADT : 128 * PADN;
    constexpr int SBe = TRB ? 32 * PADT : 128 * PADN;
    constexpr int STE = 2 * SAe + 2 * SBe;

    const int tid = threadIdx.x, lane = tid & 31, warp = tid >> 5;
    const int wm = (warp & 1) * 64, wn = (warp >> 1) * 32;
    const int m0 = blockIdx.y * 128, n0 = blockIdx.x * 128;

    const uint32_t sbase = smem_u32(smem);

    const int nt_row = lane & 15, nt_col = (lane >> 4) * 8;
    const int tr_krow = (lane & 7) + ((lane & 16) >> 1);
    const int tr_mcol = lane & 8;

    int aoff[2], boff[2];
    size_t agof[2], bgof[2];
#pragma unroll
    for (int i = 0; i < 2; i++) {
        int idx = tid + i * 256;
        if (TRA) { int kr = idx >> 4, c = (idx & 15) * 8;
            aoff[i] = kr * PADT + c;  agof[i] = (size_t)kr * lda + m0 + c; }
        else     { int r = idx >> 2,  c = (idx & 3) * 8;
            aoff[i] = r * PADN + c;   agof[i] = (size_t)(m0 + r) * lda + c; }
        if (TRB) { int kr = idx >> 4, c = (idx & 15) * 8;
            boff[i] = kr * PADT + c;  bgof[i] = (size_t)kr * ldb + n0 + c; }
        else     { int r = idx >> 2,  c = (idx & 3) * 8;
            boff[i] = r * PADN + c;   bgof[i] = (size_t)(n0 + r) * ldb + c; }
    }

    auto issue_stage = [&](int buf, int k0) {
        uint32_t base = sbase + (uint32_t)(buf * STE) * 2;
        size_t ka = TRA ? (size_t)k0 * lda : (size_t)k0;
        size_t kb = TRB ? (size_t)k0 * ldb : (size_t)k0;
#pragma unroll
        for (int i = 0; i < 2; i++) {
            cp16(base + (uint32_t)aoff[i] * 2,                   Ah + agof[i] + ka);
            cp16(base + (uint32_t)(SAe + aoff[i]) * 2,           Al + agof[i] + ka);
            cp16(base + (uint32_t)(2 * SAe + boff[i]) * 2,       Bh + bgof[i] + kb);
            cp16(base + (uint32_t)(2 * SAe + SBe + boff[i]) * 2, Bl + bgof[i] + kb);
        }
        CP_COMMIT();
    };

    float acc[4][4][4] = {};

    const int NSTEP = Kred / 32;
    issue_stage(0, 0);

    for (int s = 0; s < NSTEP; s++) {
        const int buf = s & 1;
        // issue s+1 BEFORE waiting on s: copy overlaps the wait + barrier.
        // Target buffer (1-buf) was fully consumed in stage s-1, protected by
        // that stage's trailing __syncthreads.
        if (s + 1 < NSTEP) { issue_stage(1 - buf, (s + 1) * 32); CP_WAIT1(); }
        else               { CP_WAIT0(); }
        __syncthreads();

        const uint32_t aH = sbase + (uint32_t)(buf * STE) * 2;
        const uint32_t aL = aH + SAe * 2;
        const uint32_t bH = aH + 2 * SAe * 2;
        const uint32_t bL = bH + SBe * 2;

#pragma unroll
        for (int kk = 0; kk < 32; kk += 16) {
            uint32_t bh[2][4], bl[2][4];
#pragma unroll
            for (int nj = 0; nj < 2; nj++) {
                if (TRB) {
                    uint32_t off = (uint32_t)((kk + tr_krow) * PADT + wn + nj * 16 + tr_mcol) * 2;
                    ldsm_x4t(bh[nj], bH + off);
                    ldsm_x4t(bl[nj], bL + off);
                } else {
                    uint32_t off = (uint32_t)((wn + nj * 16 + nt_row) * PADN + kk + nt_col) * 2;
                    ldsm_x4(bh[nj], bH + off);
                    ldsm_x4(bl[nj], bL + off);
                }
            }
#pragma unroll
            for (int mi = 0; mi < 4; mi++) {
                uint32_t ah[4], al[4];
                if (TRA) {
                    uint32_t off = (uint32_t)((kk + tr_krow) * PADT + wm + mi * 16 + tr_mcol) * 2;
                    ldsm_x4t(ah, aH + off);
                    ldsm_x4t(al, aL + off);
                } else {
                    uint32_t off = (uint32_t)((wm + mi * 16 + nt_row) * PADN + kk + nt_col) * 2;
                    ldsm_x4(ah, aH + off);
                    ldsm_x4(al, aL + off);
                }
#pragma unroll
                for (int ni = 0; ni < 4; ni++) {
                    uint32_t b0 = bh[ni >> 1][ni & 1], b1 = bh[ni >> 1][(ni & 1) + 2];
                    mma16816(acc[mi][ni], ah, b0, b1);
                    mma16816(acc[mi][ni], al, b0, b1);
                    mma16816(acc[mi][ni], ah, bl[ni >> 1][ni & 1], bl[ni >> 1][(ni & 1) + 2]);
                }
            }
        }
        __syncthreads();
    }

#pragma unroll
    for (int mi = 0; mi < 4; mi++) {
#pragma unroll
        for (int ni = 0; ni < 4; ni++) {
            int n = n0 + wn + ni * 8 + (lane & 3) * 2;
            int m = m0 + wm + mi * 16 + (lane >> 2);
            float bx = 0.f, by = 0.f;
            if (bias) { float2 bv = *(const float2*)(bias + n); bx = bv.x; by = bv.y; }
            float v00 = acc[mi][ni][0] * scale + bx, v01 = acc[mi][ni][1] * scale + by;
            float v10 = acc[mi][ni][2] * scale + bx, v11 = acc[mi][ni][3] * scale + by;
            if (OUTBF) {
                uint32_t h0, l0, h1, l1;
                pack_hl(v00, v01, h0, l0);
                pack_hl(v10, v11, h1, l1);
                *(uint32_t*)(Ch + (size_t)m * ldc + n)       = h0;
                *(uint32_t*)(Cl + (size_t)m * ldc + n)       = l0;
                *(uint32_t*)(Ch + (size_t)(m + 8) * ldc + n) = h1;
                *(uint32_t*)(Cl + (size_t)(m + 8) * ldc + n) = l1;
            } else {
                float* p0 = Cf + (size_t)m * ldc + n;
                float* p1 = Cf + (size_t)(m + 8) * ldc + n;
                p0[0] = v00; p0[1] = v01;
                p1[0] = v10; p1[1] = v11;
            }
        }
    }
}

// ---------------- wrappers --------------------------------------------------
__global__ __launch_bounds__(256, 2)
void k_gemm1(const bf16* xh, const bf16* xl, const bf16* wh, const bf16* wl,
             const float* bias, bf16* qkvh, bf16* qkvl)
{
    extern __shared__ char sm[];
    ghl_core<0, 1, 1>(xh, xl, D_, wh, wl, N3_,
                      nullptr, qkvh, qkvl, N3_, D_, 1.f, bias, sm);
}

__global__ __launch_bounds__(256, 2)
void k_proj(const bf16* hkh, const bf16* hkl, const bf16* hvh, const bf16* hvl,
            const bf16* qkvh, const bf16* qkvl,
            bf16* kph, bf16* kpl, bf16* vph, bf16* vpl)
{
    extern __shared__ char sm[];
    int p = blockIdx.z & 1, b = blockIdx.z >> 1;
    const bf16* Ah = p ? hvh : hkh;
    const bf16* Al = p ? hvl : hkl;
    const bf16* Bh = qkvh + (size_t)b * L_ * N3_ + (1 + p) * D_;
    const bf16* Bl = qkvl + (size_t)b * L_ * N3_ + (1 + p) * D_;
    bf16* Ch = (p ? vph : kph) + (size_t)b * K_ * D_;
    bf16* Cl = (p ? vpl : kpl) + (size_t)b * K_ * D_;
    ghl_core<1, 1, 1>(Ah, Al, K_, Bh, Bl, N3_,
                      nullptr, Ch, Cl, D_, L_, 1.f, nullptr, sm);
}

__global__ __launch_bounds__(256, 2)
void k_scores(const bf16* qkvh, const bf16* qkvl, const bf16* kph, const bf16* kpl,
              float* sc)
{
    extern __shared__ char sm[];
    int b = blockIdx.z;
    ghl_core<0, 0, 0>(qkvh + (size_t)b * L_ * N3_, qkvl + (size_t)b * L_ * N3_, N3_,
                      kph + (size_t)b * K_ * D_, kpl + (size_t)b * K_ * D_, D_,
                      sc + (size_t)b * L_ * K_, nullptr, nullptr, K_,
                      D_, 0.03125f, nullptr, sm);
}

__global__ __launch_bounds__(256, 2)
void k_out(const bf16* ph, const bf16* pl, const bf16* vph, const bf16* vpl,
           float* out)
{
    extern __shared__ char sm[];
    int b = blockIdx.z;
    ghl_core<0, 1, 0>(ph + (size_t)b * L_ * K_, pl + (size_t)b * L_ * K_, K_,
                      vph + (size_t)b * K_ * D_, vpl + (size_t)b * K_ * D_, D_,
                      out + (size_t)b * L_ * D_, nullptr, nullptr, D_,
                      K_, 1.f, nullptr, sm);
}

// ---------------------------------------------------------------------------
// softmax over K=256 -> hi/lo bf16 weights
// ---------------------------------------------------------------------------
__global__ __launch_bounds__(256)
void softmax_ps(const float* __restrict__ S, bf16* __restrict__ Ph, bf16* __restrict__ Pl)
{
    int warp = threadIdx.x >> 5, lane = threadIdx.x & 31;
    size_t row = (size_t)blockIdx.x * 8 + warp;
    const float* p = S + row * K_;

    float v[8];
    float m = -INFINITY;
#pragma unroll
    for (int i = 0; i < 8; i++) { v[i] = p[lane + i * 32]; m = fmaxf(m, v[i]); }
#pragma unroll
    for (int o = 16; o > 0; o >>= 1) m = fmaxf(m, __shfl_xor_sync(0xffffffffu, m, o));
    float s = 0.f;
#pragma unroll
    for (int i = 0; i < 8; i++) { v[i] = __expf(v[i] - m); s += v[i]; }
#pragma unroll
    for (int o = 16; o > 0; o >>= 1) s += __shfl_xor_sync(0xffffffffu, s, o);
    float inv = 1.f / s;
#pragma unroll
    for (int i = 0; i < 8; i++) {
        int kc = lane + i * 32;
        float w = v[i] * inv;
        bf16 h = __float2bfloat16_rn(w);
        bf16 lo = __float2bfloat16_rn(w - __bfloat162float(h));
        Ph[row * K_ + kc] = h;
        Pl[row * K_ + kc] = lo;
    }
}

// ---------------------------------------------------------------------------
extern "C" void kernel_launch(void* const* d_in, const int* in_sizes, int n_in,
                              void* d_out, int out_size)
{
    const float* x    = (const float*)d_in[0];
    const float* W    = (const float*)d_in[1];
    const float* bias = (const float*)d_in[2];
    const float* Hk   = (const float*)d_in[3];
    const float* Hv   = (const float*)d_in[4];
    float*       out  = (float*)d_out;

    bf16 *xh, *xl, *wh, *wl, *hkh, *hkl, *hvh, *hvl;
    bf16 *qkvh, *qkvl, *kph, *kpl, *vph, *vpl, *ph, *pl;
    float *sc;
    cudaGetSymbolAddress((void**)&xh, g_xh);   cudaGetSymbolAddress((void**)&xl, g_xl);
    cudaGetSymbolAddress((void**)&wh, g_wh);   cudaGetSymbolAddress((void**)&wl, g_wl);
    cudaGetSymbolAddress((void**)&hkh, g_hkh); cudaGetSymbolAddress((void**)&hkl, g_hkl);
    cudaGetSymbolAddress((void**)&hvh, g_hvh); cudaGetSymbolAddress((void**)&hvl, g_hvl);
    cudaGetSymbolAddress((void**)&qkvh, g_qkvh); cudaGetSymbolAddress((void**)&qkvl, g_qkvl);
    cudaGetSymbolAddress((void**)&kph, g_kph); cudaGetSymbolAddress((void**)&kpl, g_kpl);
    cudaGetSymbolAddress((void**)&vph, g_vph); cudaGetSymbolAddress((void**)&vpl, g_vpl);
    cudaGetSymbolAddress((void**)&ph, g_ph);   cudaGetSymbolAddress((void**)&pl, g_pl);
    cudaGetSymbolAddress((void**)&sc, g_sc);

    // NS=2 stages (round-8 champion sizes)
    const int SZ_NT = 2 * (2 * 128 * PADN + 2 * 32 * PADT) * 2;   // 75776
    const int SZ_TT = 2 * (2 * 32 * PADT + 2 * 32 * PADT) * 2;    // 69632
    const int SZ_NN = 2 * (2 * 128 * PADN + 2 * 128 * PADN) * 2;  // 81920
    cudaFuncSetAttribute(k_gemm1,  cudaFuncAttributeMaxDynamicSharedMemorySize, SZ_NT);
    cudaFuncSetAttribute(k_proj,   cudaFuncAttributeMaxDynamicSharedMemorySize, SZ_TT);
    cudaFuncSetAttribute(k_scores, cudaFuncAttributeMaxDynamicSharedMemorySize, SZ_NN);
    cudaFuncSetAttribute(k_out,    cudaFuncAttributeMaxDynamicSharedMemorySize, SZ_NT);

    presplit<<<(size_t)BL_ * D_ / 1024, 256>>>(x, xh, xl);
    presplit<<<(size_t)D_ * N3_ / 1024, 256>>>(W, wh, wl);
    presplit<<<(size_t)L_ * K_ / 1024, 256>>>(Hk, hkh, hkl);
    presplit<<<(size_t)L_ * K_ / 1024, 256>>>(Hv, hvh, hvl);

    k_gemm1<<<dim3(N3_ / 128, BL_ / 128, 1), 256, SZ_NT>>>(xh, xl, wh, wl, bias, qkvh, qkvl);

    k_proj<<<dim3(D_ / 128, K_ / 128, 2 * B_), 256, SZ_TT>>>(
        hkh, hkl, hvh, hvl, qkvh, qkvl, kph, kpl, vph, vpl);

    k_scores<<<dim3(K_ / 128, L_ / 128, B_), 256, SZ_NN>>>(qkvh, qkvl, kph, kpl, sc);

    softmax_ps<<<BL_ / 8, 256>>>(sc, ph, pl);

    k_out<<<dim3(D_ / 128, L_ / 128, B_), 256, SZ_NT>>>(ph, pl, vph, vpl, out);
}

// round 12
// speedup vs baseline: 1.0880x; 1.0067x over previous
#include <cuda_runtime.h>
#include <cuda_bf16.h>
#include <math.h>
#include <stdint.h>

#define B_  8
#define L_  4096
#define D_  1024
#define K_  256
#define N3_ 3072
#define BL_ (B_*L_)

typedef __nv_bfloat16 bf16;

// ---------------- scratch (__device__ globals) ------------------------------
__device__ bf16  g_xh [(size_t)BL_ * D_],  g_xl [(size_t)BL_ * D_];
__device__ bf16  g_wh [(size_t)D_ * N3_],  g_wl [(size_t)D_ * N3_];
__device__ bf16  g_hkh[(size_t)L_ * K_],   g_hkl[(size_t)L_ * K_];
__device__ bf16  g_hvh[(size_t)L_ * K_],   g_hvl[(size_t)L_ * K_];
__device__ bf16  g_qkvh[(size_t)BL_ * N3_], g_qkvl[(size_t)BL_ * N3_];
__device__ bf16  g_kph[(size_t)B_ * K_ * D_], g_kpl[(size_t)B_ * K_ * D_];
__device__ bf16  g_vph[(size_t)B_ * K_ * D_], g_vpl[(size_t)B_ * K_ * D_];
__device__ float g_sc [(size_t)BL_ * K_];
__device__ bf16  g_ph [(size_t)BL_ * K_],  g_pl [(size_t)BL_ * K_];

// ---------------- helpers ---------------------------------------------------
__device__ __forceinline__ uint32_t smem_u32(const void* p) {
    uint32_t a;
    asm("{ .reg .u64 t; cvta.to.shared.u64 t, %1; cvt.u32.u64 %0, t; }" : "=r"(a) : "l"(p));
    return a;
}
__device__ __forceinline__ void cp16(uint32_t saddr, const void* gaddr) {
    asm volatile("cp.async.cg.shared.global [%0], [%1], 16;" :: "r"(saddr), "l"(gaddr));
}
#define CP_COMMIT() asm volatile("cp.async.commit_group;" ::: "memory")
#define CP_WAIT0()  asm volatile("cp.async.wait_group 0;" ::: "memory")
#define CP_WAIT1()  asm volatile("cp.async.wait_group 1;" ::: "memory")

__device__ __forceinline__ void ldsm_x4(uint32_t* r, uint32_t addr) {
    asm volatile("ldmatrix.sync.aligned.m8n8.x4.shared.b16 {%0,%1,%2,%3}, [%4];"
                 : "=r"(r[0]), "=r"(r[1]), "=r"(r[2]), "=r"(r[3]) : "r"(addr));
}
__device__ __forceinline__ void ldsm_x4t(uint32_t* r, uint32_t addr) {
    asm volatile("ldmatrix.sync.aligned.m8n8.x4.trans.shared.b16 {%0,%1,%2,%3}, [%4];"
                 : "=r"(r[0]), "=r"(r[1]), "=r"(r[2]), "=r"(r[3]) : "r"(addr));
}
__device__ __forceinline__ void mma16816(float* d, const uint32_t* a, uint32_t b0, uint32_t b1) {
    asm volatile("mma.sync.aligned.m16n8k16.row.col.f32.bf16.bf16.f32 "
                 "{%0,%1,%2,%3}, {%4,%5,%6,%7}, {%8,%9}, {%0,%1,%2,%3};"
                 : "+f"(d[0]), "+f"(d[1]), "+f"(d[2]), "+f"(d[3])
                 : "r"(a[0]), "r"(a[1]), "r"(a[2]), "r"(a[3]), "r"(b0), "r"(b1));
}
__device__ __forceinline__ void pack_hl(float a, float b, uint32_t& h, uint32_t& l) {
    __nv_bfloat162 hv = __floats2bfloat162_rn(a, b);
    float2 hf = __bfloat1622float2(hv);
    __nv_bfloat162 lv = __floats2bfloat162_rn(a - hf.x, b - hf.y);
    h = *(uint32_t*)&hv;
    l = *(uint32_t*)&lv;
}

// ---------------------------------------------------------------------------
// presplit: fp32 -> hi/lo bf16 (single array)
// ---------------------------------------------------------------------------
__global__ __launch_bounds__(256)
void presplit(const float* __restrict__ src, bf16* __restrict__ h, bf16* __restrict__ l)
{
    size_t i = ((size_t)blockIdx.x * 256 + threadIdx.x) * 4;
    float4 v = *(const float4*)(src + i);
    uint32_t h0, l0, h1, l1;
    pack_hl(v.x, v.y, h0, l0);
    pack_hl(v.z, v.w, h1, l1);
    *(uint2*)(h + i) = make_uint2(h0, h1);
    *(uint2*)(l + i) = make_uint2(l0, l1);
}

// presplit for the two H matrices in one launch (z selects)
__global__ __launch_bounds__(256)
void presplit_h(const float* __restrict__ Hk, const float* __restrict__ Hv,
                bf16* __restrict__ kh, bf16* __restrict__ kl,
                bf16* __restrict__ vh, bf16* __restrict__ vl)
{
    const float* src = blockIdx.z ? Hv : Hk;
    bf16* h = blockIdx.z ? vh : kh;
    bf16* l = blockIdx.z ? vl : kl;
    size_t i = ((size_t)blockIdx.x * 256 + threadIdx.x) * 4;
    float4 v = *(const float4*)(src + i);
    uint32_t h0, l0, h1, l1;
    pack_hl(v.x, v.y, h0, l0);
    pack_hl(v.z, v.w, h1, l1);
    *(uint2*)(h + i) = make_uint2(h0, h1);
    *(uint2*)(l + i) = make_uint2(l0, l1);
}

// ---------------------------------------------------------------------------
// Core bf16 hi/lo mma GEMM, NS=2 cp.async, issue-before-wait schedule.
// CTA tile 128x128, 256 threads (warps 2m x 4n, warp tile 64x32), K-step 32.
// ---------------------------------------------------------------------------
#define PADN 40
#define PADT 136

template<int TRA, int TRB, int OUTBF>
__device__ __forceinline__ void ghl_core(
    const bf16* __restrict__ Ah, const bf16* __restrict__ Al, int lda,
    const bf16* __restrict__ Bh, const bf16* __restrict__ Bl, int ldb,
    float* __restrict__ Cf, bf16* __restrict__ Ch, bf16* __restrict__ Cl, int ldc,
    int Kred, float scale, const float* __restrict__ bias, char* smem)
{
    constexpr int SAe = TRA ? 32 * PADT : 128 * PADN;
    constexpr int SBe = TRB ? 32 * PADT : 128 * PADN;
    constexpr int STE = 2 * SAe + 2 * SBe;

    const int tid = threadIdx.x, lane = tid & 31, warp = tid >> 5;
    const int wm = (warp & 1) * 64, wn = (warp >> 1) * 32;
    const int m0 = blockIdx.y * 128, n0 = blockIdx.x * 128;

    const uint32_t sbase = smem_u32(smem);

    const int nt_row = lane & 15, nt_col = (lane >> 4) * 8;
    const int tr_krow = (lane & 7) + ((lane & 16) >> 1);
    const int tr_mcol = lane & 8;

    int aoff[2], boff[2];
    size_t agof[2], bgof[2];
#pragma unroll
    for (int i = 0; i < 2; i++) {
        int idx = tid + i * 256;
        if (TRA) { int kr = idx >> 4, c = (idx & 15) * 8;
            aoff[i] = kr * PADT + c;  agof[i] = (size_t)kr * lda + m0 + c; }
        else     { int r = idx >> 2,  c = (idx & 3) * 8;
            aoff[i] = r * PADN + c;   agof[i] = (size_t)(m0 + r) * lda + c; }
        if (TRB) { int kr = idx >> 4, c = (idx & 15) * 8;
            boff[i] = kr * PADT + c;  bgof[i] = (size_t)kr * ldb + n0 + c; }
        else     { int r = idx >> 2,  c = (idx & 3) * 8;
            boff[i] = r * PADN + c;   bgof[i] = (size_t)(n0 + r) * ldb + c; }
    }

    auto issue_stage = [&](int buf, int k0) {
        uint32_t base = sbase + (uint32_t)(buf * STE) * 2;
        size_t ka = TRA ? (size_t)k0 * lda : (size_t)k0;
        size_t kb = TRB ? (size_t)k0 * ldb : (size_t)k0;
#pragma unroll
        for (int i = 0; i < 2; i++) {
            cp16(base + (uint32_t)aoff[i] * 2,                   Ah + agof[i] + ka);
            cp16(base + (uint32_t)(SAe + aoff[i]) * 2,           Al + agof[i] + ka);
            cp16(base + (uint32_t)(2 * SAe + boff[i]) * 2,       Bh + bgof[i] + kb);
            cp16(base + (uint32_t)(2 * SAe + SBe + boff[i]) * 2, Bl + bgof[i] + kb);
        }
        CP_COMMIT();
    };

    float acc[4][4][4] = {};

    const int NSTEP = Kred / 32;
    issue_stage(0, 0);

    for (int s = 0; s < NSTEP; s++) {
        const int buf = s & 1;
        if (s + 1 < NSTEP) { issue_stage(1 - buf, (s + 1) * 32); CP_WAIT1(); }
        else               { CP_WAIT0(); }
        __syncthreads();

        const uint32_t aH = sbase + (uint32_t)(buf * STE) * 2;
        const uint32_t aL = aH + SAe * 2;
        const uint32_t bH = aH + 2 * SAe * 2;
        const uint32_t bL = bH + SBe * 2;

#pragma unroll
        for (int kk = 0; kk < 32; kk += 16) {
            uint32_t bh[2][4], bl[2][4];
#pragma unroll
            for (int nj = 0; nj < 2; nj++) {
                if (TRB) {
                    uint32_t off = (uint32_t)((kk + tr_krow) * PADT + wn + nj * 16 + tr_mcol) * 2;
                    ldsm_x4t(bh[nj], bH + off);
                    ldsm_x4t(bl[nj], bL + off);
                } else {
                    uint32_t off = (uint32_t)((wn + nj * 16 + nt_row) * PADN + kk + nt_col) * 2;
                    ldsm_x4(bh[nj], bH + off);
                    ldsm_x4(bl[nj], bL + off);
                }
            }
#pragma unroll
            for (int mi = 0; mi < 4; mi++) {
                uint32_t ah[4], al[4];
                if (TRA) {
                    uint32_t off = (uint32_t)((kk + tr_krow) * PADT + wm + mi * 16 + tr_mcol) * 2;
                    ldsm_x4t(ah, aH + off);
                    ldsm_x4t(al, aL + off);
                } else {
                    uint32_t off = (uint32_t)((wm + mi * 16 + nt_row) * PADN + kk + nt_col) * 2;
                    ldsm_x4(ah, aH + off);
                    ldsm_x4(al, aL + off);
                }
#pragma unroll
                for (int ni = 0; ni < 4; ni++) {
                    uint32_t b0 = bh[ni >> 1][ni & 1], b1 = bh[ni >> 1][(ni & 1) + 2];
                    mma16816(acc[mi][ni], ah, b0, b1);
                    mma16816(acc[mi][ni], al, b0, b1);
                    mma16816(acc[mi][ni], ah, bl[ni >> 1][ni & 1], bl[ni >> 1][(ni & 1) + 2]);
                }
            }
        }
        __syncthreads();
    }

#pragma unroll
    for (int mi = 0; mi < 4; mi++) {
#pragma unroll
        for (int ni = 0; ni < 4; ni++) {
            int n = n0 + wn + ni * 8 + (lane & 3) * 2;
            int m = m0 + wm + mi * 16 + (lane >> 2);
            float bx = 0.f, by = 0.f;
            if (bias) { float2 bv = *(const float2*)(bias + n); bx = bv.x; by = bv.y; }
            float v00 = acc[mi][ni][0] * scale + bx, v01 = acc[mi][ni][1] * scale + by;
            float v10 = acc[mi][ni][2] * scale + bx, v11 = acc[mi][ni][3] * scale + by;
            if (OUTBF) {
                uint32_t h0, l0, h1, l1;
                pack_hl(v00, v01, h0, l0);
                pack_hl(v10, v11, h1, l1);
                *(uint32_t*)(Ch + (size_t)m * ldc + n)       = h0;
                *(uint32_t*)(Cl + (size_t)m * ldc + n)       = l0;
                *(uint32_t*)(Ch + (size_t)(m + 8) * ldc + n) = h1;
                *(uint32_t*)(Cl + (size_t)(m + 8) * ldc + n) = l1;
            } else {
                *(float2*)(Cf + (size_t)m * ldc + n)       = make_float2(v00, v01);
                *(float2*)(Cf + (size_t)(m + 8) * ldc + n) = make_float2(v10, v11);
            }
        }
    }
}

// ---------------- wrappers --------------------------------------------------
__global__ __launch_bounds__(256, 2)
void k_gemm1(const bf16* xh, const bf16* xl, const bf16* wh, const bf16* wl,
             const float* bias, bf16* qkvh, bf16* qkvl)
{
    extern __shared__ char sm[];
    ghl_core<0, 1, 1>(xh, xl, D_, wh, wl, N3_,
                      nullptr, qkvh, qkvl, N3_, D_, 1.f, bias, sm);
}

__global__ __launch_bounds__(256, 2)
void k_proj(const bf16* hkh, const bf16* hkl, const bf16* hvh, const bf16* hvl,
            const bf16* qkvh, const bf16* qkvl,
            bf16* kph, bf16* kpl, bf16* vph, bf16* vpl)
{
    extern __shared__ char sm[];
    int p = blockIdx.z & 1, b = blockIdx.z >> 1;
    const bf16* Ah = p ? hvh : hkh;
    const bf16* Al = p ? hvl : hkl;
    const bf16* Bh = qkvh + (size_t)b * L_ * N3_ + (1 + p) * D_;
    const bf16* Bl = qkvl + (size_t)b * L_ * N3_ + (1 + p) * D_;
    bf16* Ch = (p ? vph : kph) + (size_t)b * K_ * D_;
    bf16* Cl = (p ? vpl : kpl) + (size_t)b * K_ * D_;
    ghl_core<1, 1, 1>(Ah, Al, K_, Bh, Bl, N3_,
                      nullptr, Ch, Cl, D_, L_, 1.f, nullptr, sm);
}

__global__ __launch_bounds__(256, 2)
void k_scores(const bf16* qkvh, const bf16* qkvl, const bf16* kph, const bf16* kpl,
              float* sc)
{
    extern __shared__ char sm[];
    int b = blockIdx.z;
    ghl_core<0, 0, 0>(qkvh + (size_t)b * L_ * N3_, qkvl + (size_t)b * L_ * N3_, N3_,
                      kph + (size_t)b * K_ * D_, kpl + (size_t)b * K_ * D_, D_,
                      sc + (size_t)b * L_ * K_, nullptr, nullptr, K_,
                      D_, 0.03125f, nullptr, sm);
}

__global__ __launch_bounds__(256, 2)
void k_out(const bf16* ph, const bf16* pl, const bf16* vph, const bf16* vpl,
           float* out)
{
    extern __shared__ char sm[];
    int b = blockIdx.z;
    ghl_core<0, 1, 0>(ph + (size_t)b * L_ * K_, pl + (size_t)b * L_ * K_, K_,
                      vph + (size_t)b * K_ * D_, vpl + (size_t)b * K_ * D_, D_,
                      out + (size_t)b * L_ * D_, nullptr, nullptr, D_,
                      K_, 1.f, nullptr, sm);
}

// ---------------------------------------------------------------------------
// softmax over K=256 -> hi/lo bf16 weights
// ---------------------------------------------------------------------------
__global__ __launch_bounds__(256)
void softmax_ps(const float* __restrict__ S, bf16* __restrict__ Ph, bf16* __restrict__ Pl)
{
    int warp = threadIdx.x >> 5, lane = threadIdx.x & 31;
    size_t row = (size_t)blockIdx.x * 8 + warp;
    const float* p = S + row * K_;

    float v[8];
    float m = -INFINITY;
#pragma unroll
    for (int i = 0; i < 8; i++) { v[i] = p[lane + i * 32]; m = fmaxf(m, v[i]); }
#pragma unroll
    for (int o = 16; o > 0; o >>= 1) m = fmaxf(m, __shfl_xor_sync(0xffffffffu, m, o));
    float s = 0.f;
#pragma unroll
    for (int i = 0; i < 8; i++) { v[i] = __expf(v[i] - m); s += v[i]; }
#pragma unroll
    for (int o = 16; o > 0; o >>= 1) s += __shfl_xor_sync(0xffffffffu, s, o);
    float inv = 1.f / s;
#pragma unroll
    for (int i = 0; i < 8; i++) {
        int kc = lane + i * 32;
        float w = v[i] * inv;
        bf16 h = __float2bfloat16_rn(w);
        bf16 lo = __float2bfloat16_rn(w - __bfloat162float(h));
        Ph[row * K_ + kc] = h;
        Pl[row * K_ + kc] = lo;
    }
}

// ---------------------------------------------------------------------------
extern "C" void kernel_launch(void* const* d_in, const int* in_sizes, int n_in,
                              void* d_out, int out_size)
{
    const float* x    = (const float*)d_in[0];
    const float* W    = (const float*)d_in[1];
    const float* bias = (const float*)d_in[2];
    const float* Hk   = (const float*)d_in[3];
    const float* Hv   = (const float*)d_in[4];
    float*       out  = (float*)d_out;

    bf16 *xh, *xl, *wh, *wl, *hkh, *hkl, *hvh, *hvl;
    bf16 *qkvh, *qkvl, *kph, *kpl, *vph, *vpl, *ph, *pl;
    float *sc;
    cudaGetSymbolAddress((void**)&xh, g_xh);   cudaGetSymbolAddress((void**)&xl, g_xl);
    cudaGetSymbolAddress((void**)&wh, g_wh);   cudaGetSymbolAddress((void**)&wl, g_wl);
    cudaGetSymbolAddress((void**)&hkh, g_hkh); cudaGetSymbolAddress((void**)&hkl, g_hkl);
    cudaGetSymbolAddress((void**)&hvh, g_hvh); cudaGetSymbolAddress((void**)&hvl, g_hvl);
    cudaGetSymbolAddress((void**)&qkvh, g_qkvh); cudaGetSymbolAddress((void**)&qkvl, g_qkvl);
    cudaGetSymbolAddress((void**)&kph, g_kph); cudaGetSymbolAddress((void**)&kpl, g_kpl);
    cudaGetSymbolAddress((void**)&vph, g_vph); cudaGetSymbolAddress((void**)&vpl, g_vpl);
    cudaGetSymbolAddress((void**)&ph, g_ph);   cudaGetSymbolAddress((void**)&pl, g_pl);
    cudaGetSymbolAddress((void**)&sc, g_sc);

    const int SZ_NT = 2 * (2 * 128 * PADN + 2 * 32 * PADT) * 2;   // 75776
    const int SZ_TT = 2 * (2 * 32 * PADT + 2 * 32 * PADT) * 2;    // 69632
    const int SZ_NN = 2 * (2 * 128 * PADN + 2 * 128 * PADN) * 2;  // 81920
    cudaFuncSetAttribute(k_gemm1,  cudaFuncAttributeMaxDynamicSharedMemorySize, SZ_NT);
    cudaFuncSetAttribute(k_proj,   cudaFuncAttributeMaxDynamicSharedMemorySize, SZ_TT);
    cudaFuncSetAttribute(k_scores, cudaFuncAttributeMaxDynamicSharedMemorySize, SZ_NN);
    cudaFuncSetAttribute(k_out,    cudaFuncAttributeMaxDynamicSharedMemorySize, SZ_NT);

    // Launch order chosen so launch #4 (ncu capture slot) = k_gemm1.
    presplit<<<(size_t)BL_ * D_ / 1024, 256>>>(x, xh, xl);                     // 1
    presplit<<<(size_t)D_ * N3_ / 1024, 256>>>(W, wh, wl);                     // 2
    presplit_h<<<dim3((size_t)L_ * K_ / 1024, 1, 2), 256>>>(                   // 3
        Hk, Hv, hkh, hkl, hvh, hvl);

    k_gemm1<<<dim3(N3_ / 128, BL_ / 128, 1), 256, SZ_NT>>>(                    // 4
        xh, xl, wh, wl, bias, qkvh, qkvl);

    k_proj<<<dim3(D_ / 128, K_ / 128, 2 * B_), 256, SZ_TT>>>(                  // 5
        hkh, hkl, hvh, hvl, qkvh, qkvl, kph, kpl, vph, vpl);

    k_scores<<<dim3(K_ / 128, L_ / 128, B_), 256, SZ_NN>>>(qkvh, qkvl, kph, kpl, sc); // 6

    softmax_ps<<<BL_ / 8, 256>>>(sc, ph, pl);                                  // 7

    k_out<<<dim3(D_ / 128, L_ / 128, B_), 256, SZ_NT>>>(ph, pl, vph, vpl, out); // 8
}

// round 13
// speedup vs baseline: 2.7084x; 2.4894x over previous
#include <cuda_runtime.h>
#include <cuda_bf16.h>
#include <math.h>
#include <stdint.h>

#define B_  8
#define L_  4096
#define D_  1024
#define K_  256
#define N3_ 3072
#define BL_ (B_*L_)

typedef __nv_bfloat16 bf16;

// ---------------- scratch (__device__ globals) ------------------------------
__device__ bf16  g_xh [(size_t)BL_ * D_],  g_xl [(size_t)BL_ * D_];
__device__ bf16  g_wh [(size_t)D_ * N3_],  g_wl [(size_t)D_ * N3_];
__device__ bf16  g_hkh[(size_t)L_ * K_],   g_hkl[(size_t)L_ * K_];
__device__ bf16  g_hvh[(size_t)L_ * K_],   g_hvl[(size_t)L_ * K_];
__device__ bf16  g_ykh[(size_t)B_ * K_ * D_], g_ykl[(size_t)B_ * K_ * D_];
__device__ bf16  g_yvh[(size_t)B_ * K_ * D_], g_yvl[(size_t)B_ * K_ * D_];
__device__ bf16  g_kph[(size_t)B_ * K_ * D_], g_kpl[(size_t)B_ * K_ * D_];
__device__ bf16  g_vph[(size_t)B_ * K_ * D_], g_vpl[(size_t)B_ * K_ * D_];
__device__ bf16  g_mh [(size_t)B_ * D_ * K_], g_ml [(size_t)B_ * D_ * K_];
__device__ float g_sc [(size_t)BL_ * K_];
__device__ bf16  g_ph [(size_t)BL_ * K_],  g_pl [(size_t)BL_ * K_];
__device__ float g_ck [K_], g_cv [K_];          // colsums of Hk / Hv
__device__ float g_r  [B_ * K_];                // (bq . Kp^T)/32 per batch

// ---------------- helpers ---------------------------------------------------
__device__ __forceinline__ uint32_t smem_u32(const void* p) {
    uint32_t a;
    asm("{ .reg .u64 t; cvta.to.shared.u64 t, %1; cvt.u32.u64 %0, t; }" : "=r"(a) : "l"(p));
    return a;
}
__device__ __forceinline__ void cp16(uint32_t saddr, const void* gaddr) {
    asm volatile("cp.async.cg.shared.global [%0], [%1], 16;" :: "r"(saddr), "l"(gaddr));
}
#define CP_COMMIT() asm volatile("cp.async.commit_group;" ::: "memory")
#define CP_WAIT0()  asm volatile("cp.async.wait_group 0;" ::: "memory")
#define CP_WAIT1()  asm volatile("cp.async.wait_group 1;" ::: "memory")

__device__ __forceinline__ void ldsm_x4(uint32_t* r, uint32_t addr) {
    asm volatile("ldmatrix.sync.aligned.m8n8.x4.shared.b16 {%0,%1,%2,%3}, [%4];"
                 : "=r"(r[0]), "=r"(r[1]), "=r"(r[2]), "=r"(r[3]) : "r"(addr));
}
__device__ __forceinline__ void ldsm_x4t(uint32_t* r, uint32_t addr) {
    asm volatile("ldmatrix.sync.aligned.m8n8.x4.trans.shared.b16 {%0,%1,%2,%3}, [%4];"
                 : "=r"(r[0]), "=r"(r[1]), "=r"(r[2]), "=r"(r[3]) : "r"(addr));
}
__device__ __forceinline__ void mma16816(float* d, const uint32_t* a, uint32_t b0, uint32_t b1) {
    asm volatile("mma.sync.aligned.m16n8k16.row.col.f32.bf16.bf16.f32 "
                 "{%0,%1,%2,%3}, {%4,%5,%6,%7}, {%8,%9}, {%0,%1,%2,%3};"
                 : "+f"(d[0]), "+f"(d[1]), "+f"(d[2]), "+f"(d[3])
                 : "r"(a[0]), "r"(a[1]), "r"(a[2]), "r"(a[3]), "r"(b0), "r"(b1));
}
__device__ __forceinline__ void pack_hl(float a, float b, uint32_t& h, uint32_t& l) {
    __nv_bfloat162 hv = __floats2bfloat162_rn(a, b);
    float2 hf = __bfloat1622float2(hv);
    __nv_bfloat162 lv = __floats2bfloat162_rn(a - hf.x, b - hf.y);
    h = *(uint32_t*)&hv;
    l = *(uint32_t*)&lv;
}

// ---------------------------------------------------------------------------
// presplit kernels
// ---------------------------------------------------------------------------
__global__ __launch_bounds__(256)
void presplit(const float* __restrict__ src, bf16* __restrict__ h, bf16* __restrict__ l)
{
    size_t i = ((size_t)blockIdx.x * 256 + threadIdx.x) * 4;
    float4 v = *(const float4*)(src + i);
    uint32_t h0, l0, h1, l1;
    pack_hl(v.x, v.y, h0, l0);
    pack_hl(v.z, v.w, h1, l1);
    *(uint2*)(h + i) = make_uint2(h0, h1);
    *(uint2*)(l + i) = make_uint2(l0, l1);
}

__global__ __launch_bounds__(256)
void presplit_h(const float* __restrict__ Hk, const float* __restrict__ Hv,
                bf16* __restrict__ kh, bf16* __restrict__ kl,
                bf16* __restrict__ vh, bf16* __restrict__ vl)
{
    const float* src = blockIdx.z ? Hv : Hk;
    bf16* h = blockIdx.z ? vh : kh;
    bf16* l = blockIdx.z ? vl : kl;
    size_t i = ((size_t)blockIdx.x * 256 + threadIdx.x) * 4;
    float4 v = *(const float4*)(src + i);
    uint32_t h0, l0, h1, l1;
    pack_hl(v.x, v.y, h0, l0);
    pack_hl(v.z, v.w, h1, l1);
    *(uint2*)(h + i) = make_uint2(h0, h1);
    *(uint2*)(l + i) = make_uint2(l0, l1);
}

// colsums of Hk/Hv: c[kc] = sum_l H[l,kc]
__global__ __launch_bounds__(256)
void colsum_h(const float* __restrict__ Hk, const float* __restrict__ Hv,
              float* __restrict__ ck, float* __restrict__ cv)
{
    const float* H = blockIdx.z ? Hv : Hk;
    float* c = blockIdx.z ? cv : ck;
    int kc = threadIdx.x;
    float s = 0.f;
    for (int l = 0; l < L_; l++) s += H[(size_t)l * K_ + kc];
    c[kc] = s;
}

// r[b,kc] = (sum_d bq[d] * Kp[b,kc,d]) / 32   (one warp per (b,kc))
__global__ __launch_bounds__(256)
void r_kernel(const bf16* __restrict__ kph, const bf16* __restrict__ kpl,
              const float* __restrict__ bias, float* __restrict__ r)
{
    int idx = blockIdx.x * 8 + (threadIdx.x >> 5);   // b*K_ + kc
    int lane = threadIdx.x & 31;
    const bf16* ph = kph + (size_t)idx * D_;
    const bf16* pl = kpl + (size_t)idx * D_;
    float s = 0.f;
#pragma unroll
    for (int i = 0; i < 32; i++) {
        int d = lane + i * 32;
        s += bias[d] * (__bfloat162float(ph[d]) + __bfloat162float(pl[d]));
    }
#pragma unroll
    for (int o = 16; o > 0; o >>= 1) s += __shfl_xor_sync(0xffffffffu, s, o);
    if (lane == 0) r[idx] = s * 0.03125f;
}

// ---------------------------------------------------------------------------
// Core bf16 hi/lo mma GEMM (round-8 champion mainloop).
// Epilogue extensions: per-n bias, optional rank-1 (rowv[m]*colv[n]).
// ---------------------------------------------------------------------------
#define PADN 40
#define PADT 136

template<int TRA, int TRB, int OUTBF>
__device__ __forceinline__ void ghl_core(
    const bf16* __restrict__ Ah, const bf16* __restrict__ Al, int lda,
    const bf16* __restrict__ Bh, const bf16* __restrict__ Bl, int ldb,
    float* __restrict__ Cf, bf16* __restrict__ Ch, bf16* __restrict__ Cl, int ldc,
    int Kred, float scale, const float* __restrict__ bias,
    const float* __restrict__ rowv, const float* __restrict__ colv, char* smem)
{
    constexpr int SAe = TRA ? 32 * PADT : 128 * PADN;
    constexpr int SBe = TRB ? 32 * PADT : 128 * PADN;
    constexpr int STE = 2 * SAe + 2 * SBe;

    const int tid = threadIdx.x, lane = tid & 31, warp = tid >> 5;
    const int wm = (warp & 1) * 64, wn = (warp >> 1) * 32;
    const int m0 = blockIdx.y * 128, n0 = blockIdx.x * 128;

    const uint32_t sbase = smem_u32(smem);

    const int nt_row = lane & 15, nt_col = (lane >> 4) * 8;
    const int tr_krow = (lane & 7) + ((lane & 16) >> 1);
    const int tr_mcol = lane & 8;

    int aoff[2], boff[2];
    size_t agof[2], bgof[2];
#pragma unroll
    for (int i = 0; i < 2; i++) {
        int idx = tid + i * 256;
        if (TRA) { int kr = idx >> 4, c = (idx & 15) * 8;
            aoff[i] = kr * PADT + c;  agof[i] = (size_t)kr * lda + m0 + c; }
        else     { int r = idx >> 2,  c = (idx & 3) * 8;
            aoff[i] = r * PADN + c;   agof[i] = (size_t)(m0 + r) * lda + c; }
        if (TRB) { int kr = idx >> 4, c = (idx & 15) * 8;
            boff[i] = kr * PADT + c;  bgof[i] = (size_t)kr * ldb + n0 + c; }
        else     { int r = idx >> 2,  c = (idx & 3) * 8;
            boff[i] = r * PADN + c;   bgof[i] = (size_t)(n0 + r) * ldb + c; }
    }

    auto issue_stage = [&](int buf, int k0) {
        uint32_t base = sbase + (uint32_t)(buf * STE) * 2;
        size_t ka = TRA ? (size_t)k0 * lda : (size_t)k0;
        size_t kb = TRB ? (size_t)k0 * ldb : (size_t)k0;
#pragma unroll
        for (int i = 0; i < 2; i++) {
            cp16(base + (uint32_t)aoff[i] * 2,                   Ah + agof[i] + ka);
            cp16(base + (uint32_t)(SAe + aoff[i]) * 2,           Al + agof[i] + ka);
            cp16(base + (uint32_t)(2 * SAe + boff[i]) * 2,       Bh + bgof[i] + kb);
            cp16(base + (uint32_t)(2 * SAe + SBe + boff[i]) * 2, Bl + bgof[i] + kb);
        }
        CP_COMMIT();
    };

    float acc[4][4][4] = {};

    const int NSTEP = Kred / 32;
    issue_stage(0, 0);

    for (int s = 0; s < NSTEP; s++) {
        const int buf = s & 1;
        if (s + 1 < NSTEP) { issue_stage(1 - buf, (s + 1) * 32); CP_WAIT1(); }
        else               { CP_WAIT0(); }
        __syncthreads();

        const uint32_t aH = sbase + (uint32_t)(buf * STE) * 2;
        const uint32_t aL = aH + SAe * 2;
        const uint32_t bH = aH + 2 * SAe * 2;
        const uint32_t bL = bH + SBe * 2;

#pragma unroll
        for (int kk = 0; kk < 32; kk += 16) {
            uint32_t bh[2][4], bl[2][4];
#pragma unroll
            for (int nj = 0; nj < 2; nj++) {
                if (TRB) {
                    uint32_t off = (uint32_t)((kk + tr_krow) * PADT + wn + nj * 16 + tr_mcol) * 2;
                    ldsm_x4t(bh[nj], bH + off);
                    ldsm_x4t(bl[nj], bL + off);
                } else {
                    uint32_t off = (uint32_t)((wn + nj * 16 + nt_row) * PADN + kk + nt_col) * 2;
                    ldsm_x4(bh[nj], bH + off);
                    ldsm_x4(bl[nj], bL + off);
                }
            }
#pragma unroll
            for (int mi = 0; mi < 4; mi++) {
                uint32_t ah[4], al[4];
                if (TRA) {
                    uint32_t off = (uint32_t)((kk + tr_krow) * PADT + wm + mi * 16 + tr_mcol) * 2;
                    ldsm_x4t(ah, aH + off);
                    ldsm_x4t(al, aL + off);
                } else {
                    uint32_t off = (uint32_t)((wm + mi * 16 + nt_row) * PADN + kk + nt_col) * 2;
                    ldsm_x4(ah, aH + off);
                    ldsm_x4(al, aL + off);
                }
#pragma unroll
                for (int ni = 0; ni < 4; ni++) {
                    uint32_t b0 = bh[ni >> 1][ni & 1], b1 = bh[ni >> 1][(ni & 1) + 2];
                    mma16816(acc[mi][ni], ah, b0, b1);
                    mma16816(acc[mi][ni], al, b0, b1);
                    mma16816(acc[mi][ni], ah, bl[ni >> 1][ni & 1], bl[ni >> 1][(ni & 1) + 2]);
                }
            }
        }
        __syncthreads();
    }

#pragma unroll
    for (int mi = 0; mi < 4; mi++) {
#pragma unroll
        for (int ni = 0; ni < 4; ni++) {
            int n = n0 + wn + ni * 8 + (lane & 3) * 2;
            int m = m0 + wm + mi * 16 + (lane >> 2);
            float bx = 0.f, by = 0.f;
            if (bias) { float2 bv = *(const float2*)(bias + n); bx = bv.x; by = bv.y; }
            float v00 = acc[mi][ni][0] * scale + bx, v01 = acc[mi][ni][1] * scale + by;
            float v10 = acc[mi][ni][2] * scale + bx, v11 = acc[mi][ni][3] * scale + by;
            if (rowv) {   // rank-1: rowv[m] * colv[n]
                float r0 = rowv[m], r1 = rowv[m + 8];
                float2 cv2 = *(const float2*)(colv + n);
                v00 += r0 * cv2.x;  v01 += r0 * cv2.y;
                v10 += r1 * cv2.x;  v11 += r1 * cv2.y;
            }
            if (OUTBF) {
                uint32_t h0, l0, h1, l1;
                pack_hl(v00, v01, h0, l0);
                pack_hl(v10, v11, h1, l1);
                *(uint32_t*)(Ch + (size_t)m * ldc + n)       = h0;
                *(uint32_t*)(Cl + (size_t)m * ldc + n)       = l0;
                *(uint32_t*)(Ch + (size_t)(m + 8) * ldc + n) = h1;
                *(uint32_t*)(Cl + (size_t)(m + 8) * ldc + n) = l1;
            } else {
                *(float2*)(Cf + (size_t)m * ldc + n)       = make_float2(v00, v01);
                *(float2*)(Cf + (size_t)(m + 8) * ldc + n) = make_float2(v10, v11);
            }
        }
    }
}

// ---------------- wrappers --------------------------------------------------
// G1: Y{k,v}[b] = H{k,v}^T . x[b]     (M=256, N=1024, K=4096)
__global__ __launch_bounds__(256, 2)
void k_y(const bf16* hkh, const bf16* hkl, const bf16* hvh, const bf16* hvl,
         const bf16* xh, const bf16* xl,
         bf16* ykh, bf16* ykl, bf16* yvh, bf16* yvl)
{
    extern __shared__ char sm[];
    int p = blockIdx.z & 1, b = blockIdx.z >> 1;
    const bf16* Ah = p ? hvh : hkh;
    const bf16* Al = p ? hvl : hkl;
    bf16* Ch = (p ? yvh : ykh) + (size_t)b * K_ * D_;
    bf16* Cl = (p ? yvl : ykl) + (size_t)b * K_ * D_;
    ghl_core<1, 1, 1>(Ah, Al, K_, xh + (size_t)b * L_ * D_, xl + (size_t)b * L_ * D_, D_,
                      nullptr, Ch, Cl, D_, L_, 1.f, nullptr, nullptr, nullptr, sm);
}

// G2/G3: {K,V}p[b] = Y{k,v}[b] . W{k,v} + colsum x bias   (M=256, N=1024, K=1024)
__global__ __launch_bounds__(256, 2)
void k_kvp(const bf16* ykh, const bf16* ykl, const bf16* yvh, const bf16* yvl,
           const bf16* wh, const bf16* wl, const float* bias,
           const float* ck, const float* cv,
           bf16* kph, bf16* kpl, bf16* vph, bf16* vpl)
{
    extern __shared__ char sm[];
    int p = blockIdx.z & 1, b = blockIdx.z >> 1;
    const bf16* Ah = (p ? yvh : ykh) + (size_t)b * K_ * D_;
    const bf16* Al = (p ? yvl : ykl) + (size_t)b * K_ * D_;
    const bf16* Bh = wh + (1 + p) * D_;
    const bf16* Bl = wl + (1 + p) * D_;
    bf16* Ch = (p ? vph : kph) + (size_t)b * K_ * D_;
    bf16* Cl = (p ? vpl : kpl) + (size_t)b * K_ * D_;
    ghl_core<0, 1, 1>(Ah, Al, D_, Bh, Bl, N3_,
                      nullptr, Ch, Cl, D_, D_, 1.f, nullptr,
                      p ? cv : ck, bias + (1 + p) * D_, sm);
}

// G4: M[b] = Wq . Kp[b]^T    (M=1024, N=256, K=1024)
__global__ __launch_bounds__(256, 2)
void k_m(const bf16* wh, const bf16* wl, const bf16* kph, const bf16* kpl,
         bf16* mh, bf16* ml)
{
    extern __shared__ char sm[];
    int b = blockIdx.z;
    ghl_core<0, 0, 1>(wh, wl, N3_,
                      kph + (size_t)b * K_ * D_, kpl + (size_t)b * K_ * D_, D_,
                      nullptr, mh + (size_t)b * D_ * K_, ml + (size_t)b * D_ * K_, K_,
                      D_, 1.f, nullptr, nullptr, nullptr, sm);
}

// G5: scores[b] = (x[b] . M[b]) / 32 + r[b]   (M=4096, N=256, K=1024)
__global__ __launch_bounds__(256, 2)
void k_scores2(const bf16* xh, const bf16* xl, const bf16* mh, const bf16* ml,
               const float* r, float* sc)
{
    extern __shared__ char sm[];
    int b = blockIdx.z;
    ghl_core<0, 1, 0>(xh + (size_t)b * L_ * D_, xl + (size_t)b * L_ * D_, D_,
                      mh + (size_t)b * D_ * K_, ml + (size_t)b * D_ * K_, K_,
                      sc + (size_t)b * L_ * K_, nullptr, nullptr, K_,
                      D_, 0.03125f, r + (size_t)b * K_, nullptr, nullptr, sm);
}

// G6: out[b] = P[b] . Vp[b]   (M=4096, N=1024, K=256)
__global__ __launch_bounds__(256, 2)
void k_out(const bf16* ph, const bf16* pl, const bf16* vph, const bf16* vpl,
           float* out)
{
    extern __shared__ char sm[];
    int b = blockIdx.z;
    ghl_core<0, 1, 0>(ph + (size_t)b * L_ * K_, pl + (size_t)b * L_ * K_, K_,
                      vph + (size_t)b * K_ * D_, vpl + (size_t)b * K_ * D_, D_,
                      out + (size_t)b * L_ * D_, nullptr, nullptr, D_,
                      K_, 1.f, nullptr, nullptr, nullptr, sm);
}

// ---------------------------------------------------------------------------
// softmax over K=256 -> hi/lo bf16 weights
// ---------------------------------------------------------------------------
__global__ __launch_bounds__(256)
void softmax_ps(const float* __restrict__ S, bf16* __restrict__ Ph, bf16* __restrict__ Pl)
{
    int warp = threadIdx.x >> 5, lane = threadIdx.x & 31;
    size_t row = (size_t)blockIdx.x * 8 + warp;
    const float* p = S + row * K_;

    float v[8];
    float m = -INFINITY;
#pragma unroll
    for (int i = 0; i < 8; i++) { v[i] = p[lane + i * 32]; m = fmaxf(m, v[i]); }
#pragma unroll
    for (int o = 16; o > 0; o >>= 1) m = fmaxf(m, __shfl_xor_sync(0xffffffffu, m, o));
    float s = 0.f;
#pragma unroll
    for (int i = 0; i < 8; i++) { v[i] = __expf(v[i] - m); s += v[i]; }
#pragma unroll
    for (int o = 16; o > 0; o >>= 1) s += __shfl_xor_sync(0xffffffffu, s, o);
    float inv = 1.f / s;
#pragma unroll
    for (int i = 0; i < 8; i++) {
        int kc = lane + i * 32;
        float w = v[i] * inv;
        bf16 h = __float2bfloat16_rn(w);
        bf16 lo = __float2bfloat16_rn(w - __bfloat162float(h));
        Ph[row * K_ + kc] = h;
        Pl[row * K_ + kc] = lo;
    }
}

// ---------------------------------------------------------------------------
extern "C" void kernel_launch(void* const* d_in, const int* in_sizes, int n_in,
                              void* d_out, int out_size)
{
    const float* x    = (const float*)d_in[0];
    const float* W    = (const float*)d_in[1];
    const float* bias = (const float*)d_in[2];
    const float* Hk   = (const float*)d_in[3];
    const float* Hv   = (const float*)d_in[4];
    float*       out  = (float*)d_out;

    bf16 *xh, *xl, *wh, *wl, *hkh, *hkl, *hvh, *hvl;
    bf16 *ykh, *ykl, *yvh, *yvl, *kph, *kpl, *vph, *vpl, *mh, *ml, *ph, *pl;
    float *sc, *ck, *cv, *r;
    cudaGetSymbolAddress((void**)&xh, g_xh);   cudaGetSymbolAddress((void**)&xl, g_xl);
    cudaGetSymbolAddress((void**)&wh, g_wh);   cudaGetSymbolAddress((void**)&wl, g_wl);
    cudaGetSymbolAddress((void**)&hkh, g_hkh); cudaGetSymbolAddress((void**)&hkl, g_hkl);
    cudaGetSymbolAddress((void**)&hvh, g_hvh); cudaGetSymbolAddress((void**)&hvl, g_hvl);
    cudaGetSymbolAddress((void**)&ykh, g_ykh); cudaGetSymbolAddress((void**)&ykl, g_ykl);
    cudaGetSymbolAddress((void**)&yvh, g_yvh); cudaGetSymbolAddress((void**)&yvl, g_yvl);
    cudaGetSymbolAddress((void**)&kph, g_kph); cudaGetSymbolAddress((void**)&kpl, g_kpl);
    cudaGetSymbolAddress((void**)&vph, g_vph); cudaGetSymbolAddress((void**)&vpl, g_vpl);
    cudaGetSymbolAddress((void**)&mh, g_mh);   cudaGetSymbolAddress((void**)&ml, g_ml);
    cudaGetSymbolAddress((void**)&ph, g_ph);   cudaGetSymbolAddress((void**)&pl, g_pl);
    cudaGetSymbolAddress((void**)&sc, g_sc);
    cudaGetSymbolAddress((void**)&ck, g_ck);   cudaGetSymbolAddress((void**)&cv, g_cv);
    cudaGetSymbolAddress((void**)&r, g_r);

    const int SZ_TT = 2 * (2 * 32 * PADT + 2 * 32 * PADT) * 2;    // 69632  (TRA=1,TRB=1)
    const int SZ_NT = 2 * (2 * 128 * PADN + 2 * 32 * PADT) * 2;   // 75776  (TRA=0,TRB=1)
    const int SZ_NN = 2 * (2 * 128 * PADN + 2 * 128 * PADN) * 2;  // 81920  (TRA=0,TRB=0)
    cudaFuncSetAttribute(k_y,       cudaFuncAttributeMaxDynamicSharedMemorySize, SZ_TT);
    cudaFuncSetAttribute(k_kvp,     cudaFuncAttributeMaxDynamicSharedMemorySize, SZ_NT);
    cudaFuncSetAttribute(k_m,       cudaFuncAttributeMaxDynamicSharedMemorySize, SZ_NN);
    cudaFuncSetAttribute(k_scores2, cudaFuncAttributeMaxDynamicSharedMemorySize, SZ_NT);
    cudaFuncSetAttribute(k_out,     cudaFuncAttributeMaxDynamicSharedMemorySize, SZ_NT);

    // 1-3: presplits (launch slot 4 = k_y for the ncu capture)
    presplit<<<(size_t)BL_ * D_ / 1024, 256>>>(x, xh, xl);
    presplit<<<(size_t)D_ * N3_ / 1024, 256>>>(W, wh, wl);
    presplit_h<<<dim3((size_t)L_ * K_ / 1024, 1, 2), 256>>>(Hk, Hv, hkh, hkl, hvh, hvl);

    // 4: Yk/Yv = H^T . x
    k_y<<<dim3(D_ / 128, K_ / 128, 2 * B_), 256, SZ_TT>>>(
        hkh, hkl, hvh, hvl, xh, xl, ykh, ykl, yvh, yvl);

    // 5: colsums (for bias rank-1 terms)
    colsum_h<<<dim3(1, 1, 2), 256>>>(Hk, Hv, ck, cv);

    // 6: Kp/Vp = Y . W{k,v} + colsum (x) bias
    k_kvp<<<dim3(D_ / 128, K_ / 128, 2 * B_), 256, SZ_NT>>>(
        ykh, ykl, yvh, yvl, wh, wl, bias, ck, cv, kph, kpl, vph, vpl);

    // 7: M = Wq . Kp^T
    k_m<<<dim3(K_ / 128, D_ / 128, B_), 256, SZ_NN>>>(wh, wl, kph, kpl, mh, ml);

    // 8: r = (bq . Kp^T)/32
    r_kernel<<<B_ * K_ / 8, 256>>>(kph, kpl, bias, r);

    // 9: scores = x . M / 32 + r
    k_scores2<<<dim3(K_ / 128, L_ / 128, B_), 256, SZ_NT>>>(xh, xl, mh, ml, r, sc);

    // 10: softmax
    softmax_ps<<<BL_ / 8, 256>>>(sc, ph, pl);

    // 11: out = P . Vp
    k_out<<<dim3(D_ / 128, L_ / 128, B_), 256, SZ_NT>>>(ph, pl, vph, vpl, out);
}

// round 14
// speedup vs baseline: 2.9939x; 1.1054x over previous
#include <cuda_runtime.h>
#include <cuda_bf16.h>
#include <math.h>
#include <stdint.h>

#define B_  8
#define L_  4096
#define D_  1024
#define K_  256
#define N3_ 3072
#define BL_ (B_*L_)
#define HALFL (L_/2)     // split-K half for k_y

typedef __nv_bfloat16 bf16;

// ---------------- scratch (__device__ globals) ------------------------------
__device__ bf16  g_xh [(size_t)BL_ * D_],  g_xl [(size_t)BL_ * D_];
__device__ bf16  g_wh [(size_t)D_ * N3_],  g_wl [(size_t)D_ * N3_];
__device__ bf16  g_hkh[(size_t)L_ * K_],   g_hkl[(size_t)L_ * K_];
__device__ bf16  g_hvh[(size_t)L_ * K_],   g_hvl[(size_t)L_ * K_];
__device__ float g_yp [(size_t)2 * 16 * K_ * D_];          // split-K partials
__device__ bf16  g_ykh[(size_t)B_ * K_ * D_], g_ykl[(size_t)B_ * K_ * D_];
__device__ bf16  g_yvh[(size_t)B_ * K_ * D_], g_yvl[(size_t)B_ * K_ * D_];
__device__ bf16  g_kph[(size_t)B_ * K_ * D_], g_kpl[(size_t)B_ * K_ * D_];
__device__ bf16  g_vph[(size_t)B_ * K_ * D_], g_vpl[(size_t)B_ * K_ * D_];
__device__ bf16  g_mh [(size_t)B_ * D_ * K_], g_ml [(size_t)B_ * D_ * K_];
__device__ float g_sc [(size_t)BL_ * K_];
__device__ bf16  g_ph [(size_t)BL_ * K_],  g_pl [(size_t)BL_ * K_];
__device__ float g_ck [K_], g_cv [K_];
__device__ float g_r  [B_ * K_];

// ---------------- helpers ---------------------------------------------------
__device__ __forceinline__ uint32_t smem_u32(const void* p) {
    uint32_t a;
    asm("{ .reg .u64 t; cvta.to.shared.u64 t, %1; cvt.u32.u64 %0, t; }" : "=r"(a) : "l"(p));
    return a;
}
__device__ __forceinline__ void cp16(uint32_t saddr, const void* gaddr) {
    asm volatile("cp.async.cg.shared.global [%0], [%1], 16;" :: "r"(saddr), "l"(gaddr));
}
#define CP_COMMIT() asm volatile("cp.async.commit_group;" ::: "memory")
#define CP_WAIT0()  asm volatile("cp.async.wait_group 0;" ::: "memory")
#define CP_WAIT1()  asm volatile("cp.async.wait_group 1;" ::: "memory")

__device__ __forceinline__ void ldsm_x4(uint32_t* r, uint32_t addr) {
    asm volatile("ldmatrix.sync.aligned.m8n8.x4.shared.b16 {%0,%1,%2,%3}, [%4];"
                 : "=r"(r[0]), "=r"(r[1]), "=r"(r[2]), "=r"(r[3]) : "r"(addr));
}
__device__ __forceinline__ void ldsm_x4t(uint32_t* r, uint32_t addr) {
    asm volatile("ldmatrix.sync.aligned.m8n8.x4.trans.shared.b16 {%0,%1,%2,%3}, [%4];"
                 : "=r"(r[0]), "=r"(r[1]), "=r"(r[2]), "=r"(r[3]) : "r"(addr));
}
__device__ __forceinline__ void mma16816(float* d, const uint32_t* a, uint32_t b0, uint32_t b1) {
    asm volatile("mma.sync.aligned.m16n8k16.row.col.f32.bf16.bf16.f32 "
                 "{%0,%1,%2,%3}, {%4,%5,%6,%7}, {%8,%9}, {%0,%1,%2,%3};"
                 : "+f"(d[0]), "+f"(d[1]), "+f"(d[2]), "+f"(d[3])
                 : "r"(a[0]), "r"(a[1]), "r"(a[2]), "r"(a[3]), "r"(b0), "r"(b1));
}
__device__ __forceinline__ void pack_hl(float a, float b, uint32_t& h, uint32_t& l) {
    __nv_bfloat162 hv = __floats2bfloat162_rn(a, b);
    float2 hf = __bfloat1622float2(hv);
    __nv_bfloat162 lv = __floats2bfloat162_rn(a - hf.x, b - hf.y);
    h = *(uint32_t*)&hv;
    l = *(uint32_t*)&lv;
}

// ---------------------------------------------------------------------------
// presplit kernels
// ---------------------------------------------------------------------------
__global__ __launch_bounds__(256)
void presplit(const float* __restrict__ src, bf16* __restrict__ h, bf16* __restrict__ l)
{
    size_t i = ((size_t)blockIdx.x * 256 + threadIdx.x) * 4;
    float4 v = *(const float4*)(src + i);
    uint32_t h0, l0, h1, l1;
    pack_hl(v.x, v.y, h0, l0);
    pack_hl(v.z, v.w, h1, l1);
    *(uint2*)(h + i) = make_uint2(h0, h1);
    *(uint2*)(l + i) = make_uint2(l0, l1);
}

__global__ __launch_bounds__(256)
void presplit_h(const float* __restrict__ Hk, const float* __restrict__ Hv,
                bf16* __restrict__ kh, bf16* __restrict__ kl,
                bf16* __restrict__ vh, bf16* __restrict__ vl)
{
    const float* src = blockIdx.z ? Hv : Hk;
    bf16* h = blockIdx.z ? vh : kh;
    bf16* l = blockIdx.z ? vl : kl;
    size_t i = ((size_t)blockIdx.x * 256 + threadIdx.x) * 4;
    float4 v = *(const float4*)(src + i);
    uint32_t h0, l0, h1, l1;
    pack_hl(v.x, v.y, h0, l0);
    pack_hl(v.z, v.w, h1, l1);
    *(uint2*)(h + i) = make_uint2(h0, h1);
    *(uint2*)(l + i) = make_uint2(l0, l1);
}

// parallel colsum: one block per (kc, which); block reduction over L
__global__ __launch_bounds__(256)
void colsum_h(const float* __restrict__ Hk, const float* __restrict__ Hv,
              float* __restrict__ ck, float* __restrict__ cv)
{
    __shared__ float red[256];
    const float* H = blockIdx.z ? Hv : Hk;
    float* c = blockIdx.z ? cv : ck;
    int kc = blockIdx.x;
    float s = 0.f;
    for (int l = threadIdx.x; l < L_; l += 256) s += H[(size_t)l * K_ + kc];
    red[threadIdx.x] = s;
    __syncthreads();
    for (int o = 128; o > 0; o >>= 1) {
        if (threadIdx.x < o) red[threadIdx.x] += red[threadIdx.x + o];
        __syncthreads();
    }
    if (threadIdx.x == 0) c[kc] = red[0];
}

// r[b,kc] = (sum_d bq[d] * Kp[b,kc,d]) / 32
__global__ __launch_bounds__(256)
void r_kernel(const bf16* __restrict__ kph, const bf16* __restrict__ kpl,
              const float* __restrict__ bias, float* __restrict__ r)
{
    int idx = blockIdx.x * 8 + (threadIdx.x >> 5);
    int lane = threadIdx.x & 31;
    const bf16* ph = kph + (size_t)idx * D_;
    const bf16* pl = kpl + (size_t)idx * D_;
    float s = 0.f;
#pragma unroll
    for (int i = 0; i < 32; i++) {
        int d = lane + i * 32;
        s += bias[d] * (__bfloat162float(ph[d]) + __bfloat162float(pl[d]));
    }
#pragma unroll
    for (int o = 16; o > 0; o >>= 1) s += __shfl_xor_sync(0xffffffffu, s, o);
    if (lane == 0) r[idx] = s * 0.03125f;
}

// reduce split-K partials -> hi/lo bf16 Y buffers
__global__ __launch_bounds__(256)
void reduce_y(const float* __restrict__ yp,
              bf16* __restrict__ ykh, bf16* __restrict__ ykl,
              bf16* __restrict__ yvh, bf16* __restrict__ yvl)
{
    size_t gi = ((size_t)blockIdx.x * 256 + threadIdx.x) * 4;
    int z = (int)(gi / ((size_t)K_ * D_));
    size_t off = gi - (size_t)z * K_ * D_;
    int p = z & 1, b = z >> 1;
    float4 a = *(const float4*)(yp + (size_t)z * K_ * D_ + off);
    float4 c = *(const float4*)(yp + ((size_t)16 + z) * K_ * D_ + off);
    float v0 = a.x + c.x, v1 = a.y + c.y, v2 = a.z + c.z, v3 = a.w + c.w;
    uint32_t h0, l0, h1, l1;
    pack_hl(v0, v1, h0, l0);
    pack_hl(v2, v3, h1, l1);
    bf16* dh = (p ? yvh : ykh) + (size_t)b * K_ * D_ + off;
    bf16* dl = (p ? yvl : ykl) + (size_t)b * K_ * D_ + off;
    *(uint2*)dh = make_uint2(h0, h1);
    *(uint2*)dl = make_uint2(l0, l1);
}

// ---------------------------------------------------------------------------
// Core bf16 hi/lo mma GEMM (round-8 champion mainloop).
// ---------------------------------------------------------------------------
#define PADN 40
#define PADT 136

template<int TRA, int TRB, int OUTBF>
__device__ __forceinline__ void ghl_core(
    const bf16* __restrict__ Ah, const bf16* __restrict__ Al, int lda,
    const bf16* __restrict__ Bh, const bf16* __restrict__ Bl, int ldb,
    float* __restrict__ Cf, bf16* __restrict__ Ch, bf16* __restrict__ Cl, int ldc,
    int Kred, float scale, const float* __restrict__ bias,
    const float* __restrict__ rowv, const float* __restrict__ colv, char* smem)
{
    constexpr int SAe = TRA ? 32 * PADT : 128 * PADN;
    constexpr int SBe = TRB ? 32 * PADT : 128 * PADN;
    constexpr int STE = 2 * SAe + 2 * SBe;

    const int tid = threadIdx.x, lane = tid & 31, warp = tid >> 5;
    const int wm = (warp & 1) * 64, wn = (warp >> 1) * 32;
    const int m0 = blockIdx.y * 128, n0 = blockIdx.x * 128;

    const uint32_t sbase = smem_u32(smem);

    const int nt_row = lane & 15, nt_col = (lane >> 4) * 8;
    const int tr_krow = (lane & 7) + ((lane & 16) >> 1);
    const int tr_mcol = lane & 8;

    int aoff[2], boff[2];
    size_t agof[2], bgof[2];
#pragma unroll
    for (int i = 0; i < 2; i++) {
        int idx = tid + i * 256;
        if (TRA) { int kr = idx >> 4, c = (idx & 15) * 8;
            aoff[i] = kr * PADT + c;  agof[i] = (size_t)kr * lda + m0 + c; }
        else     { int r = idx >> 2,  c = (idx & 3) * 8;
            aoff[i] = r * PADN + c;   agof[i] = (size_t)(m0 + r) * lda + c; }
        if (TRB) { int kr = idx >> 4, c = (idx & 15) * 8;
            boff[i] = kr * PADT + c;  bgof[i] = (size_t)kr * ldb + n0 + c; }
        else     { int r = idx >> 2,  c = (idx & 3) * 8;
            boff[i] = r * PADN + c;   bgof[i] = (size_t)(n0 + r) * ldb + c; }
    }

    auto issue_stage = [&](int buf, int k0) {
        uint32_t base = sbase + (uint32_t)(buf * STE) * 2;
        size_t ka = TRA ? (size_t)k0 * lda : (size_t)k0;
        size_t kb = TRB ? (size_t)k0 * ldb : (size_t)k0;
#pragma unroll
        for (int i = 0; i < 2; i++) {
            cp16(base + (uint32_t)aoff[i] * 2,                   Ah + agof[i] + ka);
            cp16(base + (uint32_t)(SAe + aoff[i]) * 2,           Al + agof[i] + ka);
            cp16(base + (uint32_t)(2 * SAe + boff[i]) * 2,       Bh + bgof[i] + kb);
            cp16(base + (uint32_t)(2 * SAe + SBe + boff[i]) * 2, Bl + bgof[i] + kb);
        }
        CP_COMMIT();
    };

    float acc[4][4][4] = {};

    const int NSTEP = Kred / 32;
    issue_stage(0, 0);

    for (int s = 0; s < NSTEP; s++) {
        const int buf = s & 1;
        if (s + 1 < NSTEP) { issue_stage(1 - buf, (s + 1) * 32); CP_WAIT1(); }
        else               { CP_WAIT0(); }
        __syncthreads();

        const uint32_t aH = sbase + (uint32_t)(buf * STE) * 2;
        const uint32_t aL = aH + SAe * 2;
        const uint32_t bH = aH + 2 * SAe * 2;
        const uint32_t bL = bH + SBe * 2;

#pragma unroll
        for (int kk = 0; kk < 32; kk += 16) {
            uint32_t bh[2][4], bl[2][4];
#pragma unroll
            for (int nj = 0; nj < 2; nj++) {
                if (TRB) {
                    uint32_t off = (uint32_t)((kk + tr_krow) * PADT + wn + nj * 16 + tr_mcol) * 2;
                    ldsm_x4t(bh[nj], bH + off);
                    ldsm_x4t(bl[nj], bL + off);
                } else {
                    uint32_t off = (uint32_t)((wn + nj * 16 + nt_row) * PADN + kk + nt_col) * 2;
                    ldsm_x4(bh[nj], bH + off);
                    ldsm_x4(bl[nj], bL + off);
                }
            }
#pragma unroll
            for (int mi = 0; mi < 4; mi++) {
                uint32_t ah[4], al[4];
                if (TRA) {
                    uint32_t off = (uint32_t)((kk + tr_krow) * PADT + wm + mi * 16 + tr_mcol) * 2;
                    ldsm_x4t(ah, aH + off);
                    ldsm_x4t(al, aL + off);
                } else {
                    uint32_t off = (uint32_t)((wm + mi * 16 + nt_row) * PADN + kk + nt_col) * 2;
                    ldsm_x4(ah, aH + off);
                    ldsm_x4(al, aL + off);
                }
#pragma unroll
                for (int ni = 0; ni < 4; ni++) {
                    uint32_t b0 = bh[ni >> 1][ni & 1], b1 = bh[ni >> 1][(ni & 1) + 2];
                    mma16816(acc[mi][ni], ah, b0, b1);
                    mma16816(acc[mi][ni], al, b0, b1);
                    mma16816(acc[mi][ni], ah, bl[ni >> 1][ni & 1], bl[ni >> 1][(ni & 1) + 2]);
                }
            }
        }
        __syncthreads();
    }

#pragma unroll
    for (int mi = 0; mi < 4; mi++) {
#pragma unroll
        for (int ni = 0; ni < 4; ni++) {
            int n = n0 + wn + ni * 8 + (lane & 3) * 2;
            int m = m0 + wm + mi * 16 + (lane >> 2);
            float bx = 0.f, by = 0.f;
            if (bias) { float2 bv = *(const float2*)(bias + n); bx = bv.x; by = bv.y; }
            float v00 = acc[mi][ni][0] * scale + bx, v01 = acc[mi][ni][1] * scale + by;
            float v10 = acc[mi][ni][2] * scale + bx, v11 = acc[mi][ni][3] * scale + by;
            if (rowv) {
                float r0 = rowv[m], r1 = rowv[m + 8];
                float2 cv2 = *(const float2*)(colv + n);
                v00 += r0 * cv2.x;  v01 += r0 * cv2.y;
                v10 += r1 * cv2.x;  v11 += r1 * cv2.y;
            }
            if (OUTBF) {
                uint32_t h0, l0, h1, l1;
                pack_hl(v00, v01, h0, l0);
                pack_hl(v10, v11, h1, l1);
                *(uint32_t*)(Ch + (size_t)m * ldc + n)       = h0;
                *(uint32_t*)(Cl + (size_t)m * ldc + n)       = l0;
                *(uint32_t*)(Ch + (size_t)(m + 8) * ldc + n) = h1;
                *(uint32_t*)(Cl + (size_t)(m + 8) * ldc + n) = l1;
            } else {
                *(float2*)(Cf + (size_t)m * ldc + n)       = make_float2(v00, v01);
                *(float2*)(Cf + (size_t)(m + 8) * ldc + n) = make_float2(v10, v11);
            }
        }
    }
}

// ---------------- wrappers --------------------------------------------------
// G1 split-K: Y partial[s, b, p] = H[s-half]^T . x[s-half]   (K=2048 per split)
__global__ __launch_bounds__(256, 2)
void k_y(const bf16* hkh, const bf16* hkl, const bf16* hvh, const bf16* hvl,
         const bf16* xh, const bf16* xl, float* yp)
{
    extern __shared__ char sm[];
    int zz = blockIdx.z;
    int split = zz >> 4, z = zz & 15;
    int p = z & 1, b = z >> 1;
    const bf16* Ah = (p ? hvh : hkh) + (size_t)(split * HALFL) * K_;
    const bf16* Al = (p ? hvl : hkl) + (size_t)(split * HALFL) * K_;
    const bf16* Bh = xh + (size_t)b * L_ * D_ + (size_t)(split * HALFL) * D_;
    const bf16* Bl = xl + (size_t)b * L_ * D_ + (size_t)(split * HALFL) * D_;
    float* Cf = yp + ((size_t)split * 16 + z) * K_ * D_;
    ghl_core<1, 1, 0>(Ah, Al, K_, Bh, Bl, D_,
                      Cf, nullptr, nullptr, D_, HALFL, 1.f, nullptr, nullptr, nullptr, sm);
}

// G2/G3: {K,V}p[b] = Y{k,v}[b] . W{k,v} + colsum x bias
__global__ __launch_bounds__(256, 2)
void k_kvp(const bf16* ykh, const bf16* ykl, const bf16* yvh, const bf16* yvl,
           const bf16* wh, const bf16* wl, const float* bias,
           const float* ck, const float* cv,
           bf16* kph, bf16* kpl, bf16* vph, bf16* vpl)
{
    extern __shared__ char sm[];
    int p = blockIdx.z & 1, b = blockIdx.z >> 1;
    const bf16* Ah = (p ? yvh : ykh) + (size_t)b * K_ * D_;
    const bf16* Al = (p ? yvl : ykl) + (size_t)b * K_ * D_;
    const bf16* Bh = wh + (1 + p) * D_;
    const bf16* Bl = wl + (1 + p) * D_;
    bf16* Ch = (p ? vph : kph) + (size_t)b * K_ * D_;
    bf16* Cl = (p ? vpl : kpl) + (size_t)b * K_ * D_;
    ghl_core<0, 1, 1>(Ah, Al, D_, Bh, Bl, N3_,
                      nullptr, Ch, Cl, D_, D_, 1.f, nullptr,
                      p ? cv : ck, bias + (1 + p) * D_, sm);
}

// G4: M[b] = Wq . Kp[b]^T
__global__ __launch_bounds__(256, 2)
void k_m(const bf16* wh, const bf16* wl, const bf16* kph, const bf16* kpl,
         bf16* mh, bf16* ml)
{
    extern __shared__ char sm[];
    int b = blockIdx.z;
    ghl_core<0, 0, 1>(wh, wl, N3_,
                      kph + (size_t)b * K_ * D_, kpl + (size_t)b * K_ * D_, D_,
                      nullptr, mh + (size_t)b * D_ * K_, ml + (size_t)b * D_ * K_, K_,
                      D_, 1.f, nullptr, nullptr, nullptr, sm);
}

// G5: scores[b] = (x[b] . M[b]) / 32 + r[b]
__global__ __launch_bounds__(256, 2)
void k_scores2(const bf16* xh, const bf16* xl, const bf16* mh, const bf16* ml,
               const float* r, float* sc)
{
    extern __shared__ char sm[];
    int b = blockIdx.z;
    ghl_core<0, 1, 0>(xh + (size_t)b * L_ * D_, xl + (size_t)b * L_ * D_, D_,
                      mh + (size_t)b * D_ * K_, ml + (size_t)b * D_ * K_, K_,
                      sc + (size_t)b * L_ * K_, nullptr, nullptr, K_,
                      D_, 0.03125f, r + (size_t)b * K_, nullptr, nullptr, sm);
}

// G6: out[b] = P[b] . Vp[b]
__global__ __launch_bounds__(256, 2)
void k_out(const bf16* ph, const bf16* pl, const bf16* vph, const bf16* vpl,
           float* out)
{
    extern __shared__ char sm[];
    int b = blockIdx.z;
    ghl_core<0, 1, 0>(ph + (size_t)b * L_ * K_, pl + (size_t)b * L_ * K_, K_,
                      vph + (size_t)b * K_ * D_, vpl + (size_t)b * K_ * D_, D_,
                      out + (size_t)b * L_ * D_, nullptr, nullptr, D_,
                      K_, 1.f, nullptr, nullptr, nullptr, sm);
}

// ---------------------------------------------------------------------------
// softmax over K=256 -> hi/lo bf16 weights
// ---------------------------------------------------------------------------
__global__ __launch_bounds__(256)
void softmax_ps(const float* __restrict__ S, bf16* __restrict__ Ph, bf16* __restrict__ Pl)
{
    int warp = threadIdx.x >> 5, lane = threadIdx.x & 31;
    size_t row = (size_t)blockIdx.x * 8 + warp;
    const float* p = S + row * K_;

    float v[8];
    float m = -INFINITY;
#pragma unroll
    for (int i = 0; i < 8; i++) { v[i] = p[lane + i * 32]; m = fmaxf(m, v[i]); }
#pragma unroll
    for (int o = 16; o > 0; o >>= 1) m = fmaxf(m, __shfl_xor_sync(0xffffffffu, m, o));
    float s = 0.f;
#pragma unroll
    for (int i = 0; i < 8; i++) { v[i] = __expf(v[i] - m); s += v[i]; }
#pragma unroll
    for (int o = 16; o > 0; o >>= 1) s += __shfl_xor_sync(0xffffffffu, s, o);
    float inv = 1.f / s;
#pragma unroll
    for (int i = 0; i < 8; i++) {
        int kc = lane + i * 32;
        float w = v[i] * inv;
        bf16 h = __float2bfloat16_rn(w);
        bf16 lo = __float2bfloat16_rn(w - __bfloat162float(h));
        Ph[row * K_ + kc] = h;
        Pl[row * K_ + kc] = lo;
    }
}

// ---------------------------------------------------------------------------
extern "C" void kernel_launch(void* const* d_in, const int* in_sizes, int n_in,
                              void* d_out, int out_size)
{
    const float* x    = (const float*)d_in[0];
    const float* W    = (const float*)d_in[1];
    const float* bias = (const float*)d_in[2];
    const float* Hk   = (const float*)d_in[3];
    const float* Hv   = (const float*)d_in[4];
    float*       out  = (float*)d_out;

    bf16 *xh, *xl, *wh, *wl, *hkh, *hkl, *hvh, *hvl;
    bf16 *ykh, *ykl, *yvh, *yvl, *kph, *kpl, *vph, *vpl, *mh, *ml, *ph, *pl;
    float *sc, *ck, *cv, *r, *yp;
    cudaGetSymbolAddress((void**)&xh, g_xh);   cudaGetSymbolAddress((void**)&xl, g_xl);
    cudaGetSymbolAddress((void**)&wh, g_wh);   cudaGetSymbolAddress((void**)&wl, g_wl);
    cudaGetSymbolAddress((void**)&hkh, g_hkh); cudaGetSymbolAddress((void**)&hkl, g_hkl);
    cudaGetSymbolAddress((void**)&hvh, g_hvh); cudaGetSymbolAddress((void**)&hvl, g_hvl);
    cudaGetSymbolAddress((void**)&ykh, g_ykh); cudaGetSymbolAddress((void**)&ykl, g_ykl);
    cudaGetSymbolAddress((void**)&yvh, g_yvh); cudaGetSymbolAddress((void**)&yvl, g_yvl);
    cudaGetSymbolAddress((void**)&kph, g_kph); cudaGetSymbolAddress((void**)&kpl, g_kpl);
    cudaGetSymbolAddress((void**)&vph, g_vph); cudaGetSymbolAddress((void**)&vpl, g_vpl);
    cudaGetSymbolAddress((void**)&mh, g_mh);   cudaGetSymbolAddress((void**)&ml, g_ml);
    cudaGetSymbolAddress((void**)&ph, g_ph);   cudaGetSymbolAddress((void**)&pl, g_pl);
    cudaGetSymbolAddress((void**)&sc, g_sc);
    cudaGetSymbolAddress((void**)&ck, g_ck);   cudaGetSymbolAddress((void**)&cv, g_cv);
    cudaGetSymbolAddress((void**)&r, g_r);
    cudaGetSymbolAddress((void**)&yp, g_yp);

    const int SZ_TT = 2 * (2 * 32 * PADT + 2 * 32 * PADT) * 2;    // 69632
    const int SZ_NT = 2 * (2 * 128 * PADN + 2 * 32 * PADT) * 2;   // 75776
    const int SZ_NN = 2 * (2 * 128 * PADN + 2 * 128 * PADN) * 2;  // 81920
    cudaFuncSetAttribute(k_y,       cudaFuncAttributeMaxDynamicSharedMemorySize, SZ_TT);
    cudaFuncSetAttribute(k_kvp,     cudaFuncAttributeMaxDynamicSharedMemorySize, SZ_NT);
    cudaFuncSetAttribute(k_m,       cudaFuncAttributeMaxDynamicSharedMemorySize, SZ_NN);
    cudaFuncSetAttribute(k_scores2, cudaFuncAttributeMaxDynamicSharedMemorySize, SZ_NT);
    cudaFuncSetAttribute(k_out,     cudaFuncAttributeMaxDynamicSharedMemorySize, SZ_NT);

    // 1-3: presplits (slot 4 = k_y for ncu)
    presplit<<<(size_t)BL_ * D_ / 1024, 256>>>(x, xh, xl);
    presplit<<<(size_t)D_ * N3_ / 1024, 256>>>(W, wh, wl);
    presplit_h<<<dim3((size_t)L_ * K_ / 1024, 1, 2), 256>>>(Hk, Hv, hkh, hkl, hvh, hvl);

    // 4: Y partials (split-K=2 -> 512 CTAs)
    k_y<<<dim3(D_ / 128, K_ / 128, 2 * 2 * B_), 256, SZ_TT>>>(
        hkh, hkl, hvh, hvl, xh, xl, yp);

    // 5: colsums (parallel)
    colsum_h<<<dim3(K_, 1, 2), 256>>>(Hk, Hv, ck, cv);

    // 6: reduce partials -> Yk/Yv hi/lo
    reduce_y<<<(size_t)16 * K_ * D_ / 1024, 256>>>(yp, ykh, ykl, yvh, yvl);

    // 7: Kp/Vp = Y . W{k,v} + colsum (x) bias
    k_kvp<<<dim3(D_ / 128, K_ / 128, 2 * B_), 256, SZ_NT>>>(
        ykh, ykl, yvh, yvl, wh, wl, bias, ck, cv, kph, kpl, vph, vpl);

    // 8: M = Wq . Kp^T
    k_m<<<dim3(K_ / 128, D_ / 128, B_), 256, SZ_NN>>>(wh, wl, kph, kpl, mh, ml);

    // 9: r = (bq . Kp^T)/32
    r_kernel<<<B_ * K_ / 8, 256>>>(kph, kpl, bias, r);

    // 10: scores = x . M / 32 + r
    k_scores2<<<dim3(K_ / 128, L_ / 128, B_), 256, SZ_NT>>>(xh, xl, mh, ml, r, sc);

    // 11: softmax
    softmax_ps<<<BL_ / 8, 256>>>(sc, ph, pl);

    // 12: out = P . Vp
    k_out<<<dim3(D_ / 128, L_ / 128, B_), 256, SZ_NT>>>(ph, pl, vph, vpl, out);
}